// round 3
// baseline (speedup 1.0000x reference)
#include <cuda_runtime.h>
#include <math.h>

// ---- problem constants ----
constexpr int Bc = 4;
constexpr int Sc = 64;
constexpr int Dc = 512;
constexpr int Hc = 8;
constexpr int Fc = 2048;
constexpr int Lc = 2;
constexpr int Vc = 32128;
constexpr int Tc = 16;
constexpr int NCH = 64;          // soft-emb v-chunks (V = 64*502 exactly)
#define NEGBIG (-1e9f)

// ---- scratch (static device globals; no allocation allowed) ----
__device__ float g_x[Bc*Sc*Dc];
__device__ float g_h[Bc*Sc*Dc];
__device__ float g_q[Bc*Sc*Dc];
__device__ float g_k[Bc*Sc*Dc];
__device__ float g_v[Bc*Sc*Dc];
__device__ float g_att[Bc*Sc*Dc];
__device__ float g_ff[Bc*Sc*Fc];
__device__ float g_hs[Bc*Sc*Dc];
__device__ float g_cK[Lc*Bc*Sc*Dc];
__device__ float g_cV[Lc*Bc*Sc*Dc];
__device__ float g_sK[Lc*Bc*Tc*Dc];
__device__ float g_sV[Lc*Bc*Tc*Dc];
__device__ float g_xd[Bc*Dc];
__device__ float g_q4[Bc*Dc];
__device__ float g_a4[Bc*Dc];
__device__ float g_f4[Bc*Fc];
__device__ float g_hn[Bc*Dc];
__device__ float g_logits[Bc*Vc];
__device__ float g_part[NCH*Bc*Dc];

// ---- embedding lookup for encoder input ----
__global__ void embed_k(const int* __restrict__ ids, const float* __restrict__ emb) {
    int bs = blockIdx.x, tid = threadIdx.x;
    int tok = ids[bs];
    for (int d = tid; d < Dc; d += 256) g_x[bs*Dc + d] = emb[tok*Dc + d];
}

// decoder start token: pad embedding (row 0)
__global__ void initdec_k(const float* __restrict__ emb) {
    int b = blockIdx.x, tid = threadIdx.x;
    for (int d = tid; d < Dc; d += 256) g_xd[b*Dc + d] = emb[d];
}

// ---- generic rmsnorm over D=512 rows ----
__global__ void rmsnorm_k(const float* __restrict__ src, float* __restrict__ dst,
                          const float* __restrict__ w) {
    int row = blockIdx.x, tid = threadIdx.x;
    __shared__ float red[256];
    const float* s = src + row*Dc;
    float p = 0.f;
    for (int d = tid; d < Dc; d += 256) { float v = s[d]; p += v*v; }
    red[tid] = p; __syncthreads();
    for (int off = 128; off > 0; off >>= 1) {
        if (tid < off) red[tid] += red[tid + off];
        __syncthreads();
    }
    float scale = rsqrtf(red[0] / (float)Dc + 1e-6f);
    for (int d = tid; d < Dc; d += 256) dst[row*Dc + d] = s[d] * scale * w[d];
}

// ---- tiled SGEMM: C[M,N] = A[M,K] @ W[K,N] (+resid, relu). M,N mult of 64, K mult of 16 ----
__global__ void gemm_k(const float* __restrict__ A, const float* __restrict__ W,
                       float* __restrict__ C, int M, int N, int K,
                       const float* __restrict__ resid, int relu) {
    __shared__ float As[16][64];
    __shared__ float Bs[16][64];
    int bm = blockIdx.y*64, bn = blockIdx.x*64;
    int tid = threadIdx.x;
    int tr = tid >> 4, tc = tid & 15;
    float acc[4][4] = {};
    for (int k0 = 0; k0 < K; k0 += 16) {
        for (int i = tid; i < 64*16; i += 256) {
            int r = i >> 4, c = i & 15;
            As[c][r] = A[(bm + r)*K + k0 + c];
        }
        for (int i = tid; i < 16*64; i += 256) {
            int r = i >> 6, c = i & 63;
            Bs[r][c] = W[(k0 + r)*N + bn + c];
        }
        __syncthreads();
        #pragma unroll
        for (int kk = 0; kk < 16; kk++) {
            float a[4], bv[4];
            #pragma unroll
            for (int i = 0; i < 4; i++) a[i] = As[kk][tr*4 + i];
            #pragma unroll
            for (int j = 0; j < 4; j++) bv[j] = Bs[kk][tc*4 + j];
            #pragma unroll
            for (int i = 0; i < 4; i++)
                #pragma unroll
                for (int j = 0; j < 4; j++) acc[i][j] += a[i]*bv[j];
        }
        __syncthreads();
    }
    #pragma unroll
    for (int i = 0; i < 4; i++)
        #pragma unroll
        for (int j = 0; j < 4; j++) {
            int r = bm + tr*4 + i, c = bn + tc*4 + j;
            float v = acc[i][j];
            if (resid) v += resid[r*N + c];
            if (relu) v = fmaxf(v, 0.f);
            C[r*N + c] = v;
        }
}

// ---- encoder attention: one block per (b,h,query), 64 threads ----
__global__ void encattn_k(const float* __restrict__ mask) {
    int blk = blockIdx.x;
    int qi = blk % Sc; int h = (blk / Sc) % Hc; int b = blk / (Sc*Hc);
    int t = threadIdx.x;  // 64
    __shared__ float qs[64], sc[64], ps[64];
    qs[t] = g_q[(b*Sc + qi)*Dc + h*64 + t];
    __syncthreads();
    const float* kr = g_k + (b*Sc + t)*Dc + h*64;
    float s = 0.f;
    #pragma unroll
    for (int d = 0; d < 64; d++) s += qs[d]*kr[d];
    s = s*0.125f + (1.0f - mask[b*Sc + t])*NEGBIG;
    sc[t] = s; __syncthreads();
    float m = -1e30f;
    for (int j = 0; j < 64; j++) m = fmaxf(m, sc[j]);
    ps[t] = expf(sc[t] - m);
    __syncthreads();
    float ssum = 0.f, o = 0.f;
    for (int j = 0; j < 64; j++) {
        ssum += ps[j];
        o += ps[j]*g_v[(b*Sc + j)*Dc + h*64 + t];
    }
    g_att[(b*Sc + qi)*Dc + h*64 + t] = o / ssum;
}

// ---- decoder 4-row GEMV: out[4,N] = (opt rmsnorm(x))[4,K] @ W[K,N] (+resid, relu)
//      blockIdx.y selects among up to 3 weight/output pairs (fused QKV) ----
__global__ void gemv4_k(const float* __restrict__ x,
                        const float* __restrict__ W0, float* __restrict__ out0, int st0,
                        const float* __restrict__ W1, float* __restrict__ out1, int st1,
                        const float* __restrict__ W2, float* __restrict__ out2, int st2,
                        int K, int N,
                        const float* __restrict__ lnw,
                        const float* __restrict__ resid, int relu) {
    __shared__ float xs[4*2048];
    __shared__ float red[256];
    __shared__ float rscale[4];
    __shared__ float redacc[256*4];
    int tid = threadIdx.x;
    const float* W = W0; float* out = out0; int outStride = st0;
    if (blockIdx.y == 1) { W = W1; out = out1; outStride = st1; }
    else if (blockIdx.y == 2) { W = W2; out = out2; outStride = st2; }
    for (int i = tid; i < 4*K; i += 256) xs[i] = x[i];
    __syncthreads();
    if (lnw) {
        for (int b = 0; b < 4; b++) {
            float p = 0.f;
            for (int k = tid; k < K; k += 256) { float v = xs[b*K + k]; p += v*v; }
            red[tid] = p; __syncthreads();
            for (int off = 128; off > 0; off >>= 1) {
                if (tid < off) red[tid] += red[tid + off];
                __syncthreads();
            }
            if (tid == 0) rscale[b] = rsqrtf(red[0] / (float)K + 1e-6f);
            __syncthreads();
        }
        for (int i = tid; i < 4*K; i += 256) {
            int b = i / K, k = i - b*K;
            xs[i] *= rscale[b]*lnw[k];
        }
        __syncthreads();
    }
    int c = tid & 63, ks = tid >> 6;
    int n = blockIdx.x*64 + c;
    float a0 = 0.f, a1 = 0.f, a2 = 0.f, a3 = 0.f;
    for (int k = ks; k < K; k += 4) {
        float w = W[k*N + n];
        a0 += xs[k]*w;
        a1 += xs[K + k]*w;
        a2 += xs[2*K + k]*w;
        a3 += xs[3*K + k]*w;
    }
    redacc[tid*4 + 0] = a0; redacc[tid*4 + 1] = a1;
    redacc[tid*4 + 2] = a2; redacc[tid*4 + 3] = a3;
    __syncthreads();
    if (ks == 0) {
        float vb[4] = {0.f, 0.f, 0.f, 0.f};
        for (int s2 = 0; s2 < 4; s2++) {
            int t2 = s2*64 + c;
            vb[0] += redacc[t2*4 + 0]; vb[1] += redacc[t2*4 + 1];
            vb[2] += redacc[t2*4 + 2]; vb[3] += redacc[t2*4 + 3];
        }
        #pragma unroll
        for (int b = 0; b < 4; b++) {
            float v = vb[b];
            if (resid) v += resid[b*Dc + n];  // residual always stride D
            if (relu) v = fmaxf(v, 0.f);
            out[b*outStride + n] = v;
        }
    }
}

// ---- decoder self-attention (KV cache, positions 0..p), block per (b,h), 64 threads ----
__global__ void decsattn_k(int l, int p) {
    int b = blockIdx.x >> 3, h = blockIdx.x & 7;
    int t = threadIdx.x;  // 64
    __shared__ float qs[64], sc[Tc], ps[Tc];
    qs[t] = g_q4[b*Dc + h*64 + t];
    __syncthreads();
    int nk = p + 1;
    const float* sK = g_sK + l*Bc*Tc*Dc;
    const float* sV = g_sV + l*Bc*Tc*Dc;
    if (t < nk) {
        const float* kr = sK + (b*Tc + t)*Dc + h*64;
        float s = 0.f;
        #pragma unroll
        for (int d = 0; d < 64; d++) s += qs[d]*kr[d];
        sc[t] = s*0.125f;
    }
    __syncthreads();
    float m = -1e30f;
    for (int j = 0; j < nk; j++) m = fmaxf(m, sc[j]);
    if (t < nk) ps[t] = expf(sc[t] - m);
    __syncthreads();
    float ssum = 0.f, o = 0.f;
    for (int j = 0; j < nk; j++) {
        ssum += ps[j];
        o += ps[j]*sV[(b*Tc + j)*Dc + h*64 + t];
    }
    g_a4[b*Dc + h*64 + t] = o / ssum;
}

// ---- decoder cross-attention over S=64 keys (precomputed), block per (b,h) ----
__global__ void deccattn_k(int l, const float* __restrict__ mask) {
    int b = blockIdx.x >> 3, h = blockIdx.x & 7;
    int t = threadIdx.x;  // 64
    __shared__ float qs[64], sc[64], ps[64];
    qs[t] = g_q4[b*Dc + h*64 + t];
    __syncthreads();
    const float* cK = g_cK + l*Bc*Sc*Dc;
    const float* cV = g_cV + l*Bc*Sc*Dc;
    const float* kr = cK + (b*Sc + t)*Dc + h*64;
    float s = 0.f;
    #pragma unroll
    for (int d = 0; d < 64; d++) s += qs[d]*kr[d];
    sc[t] = s*0.125f + (1.0f - mask[b*Sc + t])*NEGBIG;
    __syncthreads();
    float m = -1e30f;
    for (int j = 0; j < 64; j++) m = fmaxf(m, sc[j]);
    ps[t] = expf(sc[t] - m);
    __syncthreads();
    float ssum = 0.f, o = 0.f;
    for (int j = 0; j < 64; j++) {
        ssum += ps[j];
        o += ps[j]*cV[(b*Sc + j)*Dc + h*64 + t];
    }
    g_a4[b*Dc + h*64 + t] = o / ssum;
}

// ---- lm head: logits[4,V] = hn[4,D] @ lm[D,V] ----
__global__ void lmhead_k(const float* __restrict__ lm) {
    __shared__ float hs4[4*Dc];
    int tid = threadIdx.x;
    for (int i = tid; i < 4*Dc; i += 256) hs4[i] = g_hn[i];
    __syncthreads();
    int v = blockIdx.x*256 + tid;
    if (v < Vc) {
        float a0 = 0.f, a1 = 0.f, a2 = 0.f, a3 = 0.f;
        #pragma unroll 4
        for (int d = 0; d < Dc; d++) {
            float w = lm[d*Vc + v];
            a0 += hs4[d]*w; a1 += hs4[Dc + d]*w;
            a2 += hs4[2*Dc + d]*w; a3 += hs4[3*Dc + d]*w;
        }
        g_logits[v] = a0; g_logits[Vc + v] = a1;
        g_logits[2*Vc + v] = a2; g_logits[3*Vc + v] = a3;
    }
}

// ---- softmax over V + argmax, writes prob_history row + pad-flag ----
__global__ void softmax_k(float* __restrict__ out, int step, int flagOK) {
    int b = blockIdx.x, tid = threadIdx.x;  // 256 threads
    __shared__ float sm[256]; __shared__ int si[256]; __shared__ float bsum[256];
    const float* lg = g_logits + b*Vc;
    float m = -1e30f; int mi = 0;
    for (int v = tid; v < Vc; v += 256) {
        float x = lg[v];
        if (x > m) { m = x; mi = v; }
    }
    sm[tid] = m; si[tid] = mi; __syncthreads();
    for (int off = 128; off > 0; off >>= 1) {
        if (tid < off) {
            float m2 = sm[tid + off]; int i2 = si[tid + off];
            if (m2 > sm[tid] || (m2 == sm[tid] && i2 < si[tid])) { sm[tid] = m2; si[tid] = i2; }
        }
        __syncthreads();
    }
    float gm = sm[0]; int gi = si[0];
    float p = 0.f;
    for (int v = tid; v < Vc; v += 256) p += expf(lg[v] - gm);
    bsum[tid] = p; __syncthreads();
    for (int off = 128; off > 0; off >>= 1) {
        if (tid < off) bsum[tid] += bsum[tid + off];
        __syncthreads();
    }
    float inv = 1.0f / bsum[0];
    float* po = out + ((size_t)b*Tc + step)*Vc;
    for (int v = tid; v < Vc; v += 256) po[v] = expf(lg[v] - gm)*inv;
    if (tid == 0 && flagOK)
        out[(size_t)Bc*Tc*Vc + b*Tc + step] = (gi == 0) ? 1.0f : 0.0f;
}

// ---- soft embedding: partial sums of probs @ emb over v-chunks (deterministic) ----
__global__ void softemb_k(const float* __restrict__ out, int step,
                          const float* __restrict__ emb) {
    int d = blockIdx.x*128 + threadIdx.x;  // grid.x = 4
    int cz = blockIdx.y;                    // 64 chunks of 502 v's
    int v0 = cz*502, v1 = v0 + 502;
    const float* p0 = out + ((size_t)0*Tc + step)*Vc;
    const float* p1 = out + ((size_t)1*Tc + step)*Vc;
    const float* p2 = out + ((size_t)2*Tc + step)*Vc;
    const float* p3 = out + ((size_t)3*Tc + step)*Vc;
    float a0 = 0.f, a1 = 0.f, a2 = 0.f, a3 = 0.f;
    for (int v = v0; v < v1; v++) {
        float e = emb[(size_t)v*Dc + d];
        a0 += p0[v]*e; a1 += p1[v]*e; a2 += p2[v]*e; a3 += p3[v]*e;
    }
    g_part[(cz*Bc + 0)*Dc + d] = a0;
    g_part[(cz*Bc + 1)*Dc + d] = a1;
    g_part[(cz*Bc + 2)*Dc + d] = a2;
    g_part[(cz*Bc + 3)*Dc + d] = a3;
}

__global__ void reduce_k() {
    int idx = blockIdx.x*256 + threadIdx.x;  // 2048 = B*D
    float s = 0.f;
    for (int c = 0; c < NCH; c++) s += g_part[c*Bc*Dc + idx];
    g_xd[idx] = s;
}

// ======================= host =======================
extern "C" void kernel_launch(void* const* d_in, const int* in_sizes, int n_in,
                              void* d_out, int out_size) {
    const int*   ids     = (const int*)d_in[0];
    const float* mask    = (const float*)d_in[1];
    const float* emb     = (const float*)d_in[2];
    const float* enc_wq  = (const float*)d_in[3];
    const float* enc_wk  = (const float*)d_in[4];
    const float* enc_wv  = (const float*)d_in[5];
    const float* enc_wo  = (const float*)d_in[6];
    const float* enc_ln1 = (const float*)d_in[7];
    const float* enc_w1  = (const float*)d_in[8];
    const float* enc_w2  = (const float*)d_in[9];
    const float* enc_ln2 = (const float*)d_in[10];
    const float* enc_lnf = (const float*)d_in[11];
    const float* dec_sq  = (const float*)d_in[12];
    const float* dec_sk  = (const float*)d_in[13];
    const float* dec_sv  = (const float*)d_in[14];
    const float* dec_so  = (const float*)d_in[15];
    const float* dec_ln1 = (const float*)d_in[16];
    const float* dec_cq  = (const float*)d_in[17];
    const float* dec_ck  = (const float*)d_in[18];
    const float* dec_cv  = (const float*)d_in[19];
    const float* dec_co  = (const float*)d_in[20];
    const float* dec_ln2 = (const float*)d_in[21];
    const float* dec_w1  = (const float*)d_in[22];
    const float* dec_w2  = (const float*)d_in[23];
    const float* dec_ln3 = (const float*)d_in[24];
    const float* dec_lnf = (const float*)d_in[25];
    const float* lm      = (const float*)d_in[26];
    float* out = (float*)d_out;

    void* vp;
    cudaGetSymbolAddress(&vp, g_x);   float* px   = (float*)vp;
    cudaGetSymbolAddress(&vp, g_h);   float* ph   = (float*)vp;
    cudaGetSymbolAddress(&vp, g_q);   float* pq   = (float*)vp;
    cudaGetSymbolAddress(&vp, g_k);   float* pk   = (float*)vp;
    cudaGetSymbolAddress(&vp, g_v);   float* pv   = (float*)vp;
    cudaGetSymbolAddress(&vp, g_att); float* patt = (float*)vp;
    cudaGetSymbolAddress(&vp, g_ff);  float* pff  = (float*)vp;
    cudaGetSymbolAddress(&vp, g_hs);  float* phs  = (float*)vp;
    cudaGetSymbolAddress(&vp, g_cK);  float* pcK  = (float*)vp;
    cudaGetSymbolAddress(&vp, g_cV);  float* pcV  = (float*)vp;
    cudaGetSymbolAddress(&vp, g_sK);  float* psK  = (float*)vp;
    cudaGetSymbolAddress(&vp, g_sV);  float* psV  = (float*)vp;
    cudaGetSymbolAddress(&vp, g_xd);  float* pxd  = (float*)vp;
    cudaGetSymbolAddress(&vp, g_q4);  float* pq4  = (float*)vp;
    cudaGetSymbolAddress(&vp, g_a4);  float* pa4  = (float*)vp;
    cudaGetSymbolAddress(&vp, g_f4);  float* pf4  = (float*)vp;
    cudaGetSymbolAddress(&vp, g_hn);  float* phn  = (float*)vp;

    const int M = Bc*Sc;  // 256

    // ---------- encoder ----------
    embed_k<<<M, 256>>>(ids, emb);
    for (int l = 0; l < Lc; l++) {
        rmsnorm_k<<<M, 256>>>(px, ph, enc_ln1 + l*Dc);
        gemm_k<<<dim3(8, 4), 256>>>(ph, enc_wq + l*Dc*Dc, pq, M, Dc, Dc, nullptr, 0);
        gemm_k<<<dim3(8, 4), 256>>>(ph, enc_wk + l*Dc*Dc, pk, M, Dc, Dc, nullptr, 0);
        gemm_k<<<dim3(8, 4), 256>>>(ph, enc_wv + l*Dc*Dc, pv, M, Dc, Dc, nullptr, 0);
        encattn_k<<<Bc*Hc*Sc, 64>>>(mask);
        gemm_k<<<dim3(8, 4), 256>>>(patt, enc_wo + l*Dc*Dc, px, M, Dc, Dc, px, 0);
        rmsnorm_k<<<M, 256>>>(px, ph, enc_ln2 + l*Dc);
        gemm_k<<<dim3(32, 4), 256>>>(ph, enc_w1 + l*Dc*Fc, pff, M, Fc, Dc, nullptr, 1);
        gemm_k<<<dim3(8, 4), 256>>>(pff, enc_w2 + l*Fc*Dc, px, M, Dc, Fc, px, 0);
    }
    rmsnorm_k<<<M, 256>>>(px, phs, enc_lnf);

    // cross-attention K/V precompute (hs is constant over decode steps)
    for (int l = 0; l < Lc; l++) {
        gemm_k<<<dim3(8, 4), 256>>>(phs, dec_ck + l*Dc*Dc, pcK + l*Bc*Sc*Dc, M, Dc, Dc, nullptr, 0);
        gemm_k<<<dim3(8, 4), 256>>>(phs, dec_cv + l*Dc*Dc, pcV + l*Bc*Sc*Dc, M, Dc, Dc, nullptr, 0);
    }

    // ---------- decoder (incremental; exactly equivalent to full re-run) ----------
    initdec_k<<<Bc, 256>>>(emb);
    int flagOK = (out_size >= Bc*Tc*Vc + Bc*Tc) ? 1 : 0;

    for (int p = 0; p < Tc; p++) {
        for (int l = 0; l < Lc; l++) {
            const float* ln1 = dec_ln1 + l*Dc;
            // fused self-attn q,k,v for the new token (k/v written straight into cache at pos p)
            gemv4_k<<<dim3(8, 3), 256>>>(pxd,
                dec_sq + l*Dc*Dc, pq4, Dc,
                dec_sk + l*Dc*Dc, psK + l*Bc*Tc*Dc + p*Dc, Tc*Dc,
                dec_sv + l*Dc*Dc, psV + l*Bc*Tc*Dc + p*Dc, Tc*Dc,
                Dc, Dc, ln1, nullptr, 0);
            decsattn_k<<<Bc*Hc, 64>>>(l, p);
            gemv4_k<<<dim3(8, 1), 256>>>(pa4,
                dec_so + l*Dc*Dc, pxd, Dc,
                nullptr, nullptr, 0, nullptr, nullptr, 0,
                Dc, Dc, nullptr, pxd, 0);
            // cross attention
            gemv4_k<<<dim3(8, 1), 256>>>(pxd,
                dec_cq + l*Dc*Dc, pq4, Dc,
                nullptr, nullptr, 0, nullptr, nullptr, 0,
                Dc, Dc, dec_ln2 + l*Dc, nullptr, 0);
            deccattn_k<<<Bc*Hc, 64>>>(l, mask);
            gemv4_k<<<dim3(8, 1), 256>>>(pa4,
                dec_co + l*Dc*Dc, pxd, Dc,
                nullptr, nullptr, 0, nullptr, nullptr, 0,
                Dc, Dc, nullptr, pxd, 0);
            // ffn
            gemv4_k<<<dim3(32, 1), 256>>>(pxd,
                dec_w1 + l*Dc*Fc, pf4, Fc,
                nullptr, nullptr, 0, nullptr, nullptr, 0,
                Dc, Fc, dec_ln3 + l*Dc, nullptr, 1);
            gemv4_k<<<dim3(8, 1), 256>>>(pf4,
                dec_w2 + l*Fc*Dc, pxd, Dc,
                nullptr, nullptr, 0, nullptr, nullptr, 0,
                Fc, Dc, nullptr, pxd, 0);
        }
        rmsnorm_k<<<Bc, 256>>>(pxd, phn, dec_lnf);
        lmhead_k<<<(Vc + 255)/256, 256>>>(lm);
        softmax_k<<<Bc, 256>>>(out, p, flagOK);
        softemb_k<<<dim3(4, NCH), 128>>>(out, p, emb);
        reduce_k<<<8, 256>>>();
    }
}

// round 4
// speedup vs baseline: 1.5623x; 1.5623x over previous
#include <cuda_runtime.h>
#include <math.h>

// ---- problem constants ----
constexpr int Bc = 4;
constexpr int Sc = 64;
constexpr int Dc = 512;
constexpr int Hc = 8;
constexpr int Fc = 2048;
constexpr int Lc = 2;
constexpr int Vc = 32128;
constexpr int Tc = 16;
constexpr int NCH = 64;          // soft-emb v-chunks (V = 64*502 exactly)
#define NEGBIG (-1e9f)

// ---- scratch (static device globals; no allocation allowed) ----
__device__ float g_x[Bc*Sc*Dc];
__device__ float g_h[Bc*Sc*Dc];
__device__ float g_q[Bc*Sc*Dc];
__device__ float g_k[Bc*Sc*Dc];
__device__ float g_v[Bc*Sc*Dc];
__device__ float g_att[Bc*Sc*Dc];
__device__ float g_ff[Bc*Sc*Fc];
__device__ float g_hs[Bc*Sc*Dc];
__device__ float g_cK[Lc*Bc*Sc*Dc];
__device__ float g_cV[Lc*Bc*Sc*Dc];
__device__ float g_sK[Lc*Bc*Tc*Dc];
__device__ float g_sV[Lc*Bc*Tc*Dc];
__device__ float g_xd[Bc*Dc];
__device__ float g_q4[Bc*Dc];
__device__ float g_a4[Bc*Dc];
__device__ float g_f4[Bc*Fc];
__device__ float g_logits[Bc*Vc];
__device__ float g_part[NCH*Bc*Dc];

// ---- embedding lookup for encoder input + decoder start token ----
__global__ void embed_k(const int* __restrict__ ids, const float* __restrict__ emb) {
    int bs = blockIdx.x, tid = threadIdx.x;
    if (bs < Bc*Sc) {
        int tok = ids[bs];
        for (int d = tid; d < Dc; d += 256) g_x[bs*Dc + d] = emb[tok*Dc + d];
    } else {
        int b = bs - Bc*Sc;
        for (int d = tid; d < Dc; d += 256) g_xd[b*Dc + d] = emb[d];  // pad token = row 0
    }
}

// ---- generic rmsnorm over D=512 rows ----
__global__ void rmsnorm_k(const float* __restrict__ src, float* __restrict__ dst,
                          const float* __restrict__ w) {
    int row = blockIdx.x, tid = threadIdx.x;
    __shared__ float red[256];
    const float* s = src + row*Dc;
    float p = 0.f;
    for (int d = tid; d < Dc; d += 256) { float v = s[d]; p += v*v; }
    red[tid] = p; __syncthreads();
    for (int off = 128; off > 0; off >>= 1) {
        if (tid < off) red[tid] += red[tid + off];
        __syncthreads();
    }
    float scale = rsqrtf(red[0] / (float)Dc + 1e-6f);
    for (int d = tid; d < Dc; d += 256) dst[row*Dc + d] = s[d] * scale * w[d];
}

// ---- tiled SGEMM, double-buffered: C[M,N] = A[M,K] @ W[K,N] (+resid, relu).
//      blockIdx.z selects among up to 4 (W,C) pairs. M,N mult of 64, K mult of 16 ----
__global__ __launch_bounds__(256) void gemm_k(
    const float* __restrict__ A,
    const float* __restrict__ W0, float* __restrict__ C0,
    const float* __restrict__ W1, float* __restrict__ C1,
    const float* __restrict__ W2, float* __restrict__ C2,
    const float* __restrict__ W3, float* __restrict__ C3,
    int M, int N, int K,
    const float* __restrict__ resid, int relu) {
    __shared__ float As[2][16][65];
    __shared__ float Bs[2][16][65];
    int bm = blockIdx.y*64, bn = blockIdx.x*64;
    int tid = threadIdx.x;
    int tr = tid >> 4, tc = tid & 15;
    const float* W = W0; float* C = C0;
    if (blockIdx.z == 1) { W = W1; C = C1; }
    else if (blockIdx.z == 2) { W = W2; C = C2; }
    else if (blockIdx.z == 3) { W = W3; C = C3; }

    float ra[4], rb[4];
    #pragma unroll
    for (int j = 0; j < 4; j++) { int i = tid + j*256; ra[j] = A[(bm + (i>>4))*K + (i&15)]; }
    #pragma unroll
    for (int j = 0; j < 4; j++) { int i = tid + j*256; rb[j] = W[(i>>6)*N + bn + (i&63)]; }
    #pragma unroll
    for (int j = 0; j < 4; j++) { int i = tid + j*256; As[0][i&15][i>>4] = ra[j]; }
    #pragma unroll
    for (int j = 0; j < 4; j++) { int i = tid + j*256; Bs[0][i>>6][i&63] = rb[j]; }
    __syncthreads();

    float acc[4][4] = {};
    int buf = 0;
    for (int k0 = 16; k0 <= K; k0 += 16) {
        if (k0 < K) {
            #pragma unroll
            for (int j = 0; j < 4; j++) { int i = tid + j*256; ra[j] = A[(bm + (i>>4))*K + k0 + (i&15)]; }
            #pragma unroll
            for (int j = 0; j < 4; j++) { int i = tid + j*256; rb[j] = W[(k0 + (i>>6))*N + bn + (i&63)]; }
        }
        #pragma unroll
        for (int kk = 0; kk < 16; kk++) {
            float a[4], bv[4];
            #pragma unroll
            for (int i = 0; i < 4; i++) a[i] = As[buf][kk][tr*4 + i];
            #pragma unroll
            for (int j = 0; j < 4; j++) bv[j] = Bs[buf][kk][tc*4 + j];
            #pragma unroll
            for (int i = 0; i < 4; i++)
                #pragma unroll
                for (int j = 0; j < 4; j++) acc[i][j] += a[i]*bv[j];
        }
        if (k0 < K) {
            #pragma unroll
            for (int j = 0; j < 4; j++) { int i = tid + j*256; As[buf^1][i&15][i>>4] = ra[j]; }
            #pragma unroll
            for (int j = 0; j < 4; j++) { int i = tid + j*256; Bs[buf^1][i>>6][i&63] = rb[j]; }
        }
        __syncthreads();
        buf ^= 1;
    }
    #pragma unroll
    for (int i = 0; i < 4; i++)
        #pragma unroll
        for (int j = 0; j < 4; j++) {
            int r = bm + tr*4 + i, c = bn + tc*4 + j;
            float v = acc[i][j];
            if (resid) v += resid[r*N + c];
            if (relu) v = fmaxf(v, 0.f);
            C[r*N + c] = v;
        }
}

// ---- encoder attention: one block per (b,h,query), 64 threads ----
__global__ void encattn_k(const float* __restrict__ mask) {
    int blk = blockIdx.x;
    int qi = blk % Sc; int h = (blk / Sc) % Hc; int b = blk / (Sc*Hc);
    int t = threadIdx.x;  // 64
    __shared__ float qs[64], sc[64], ps[64];
    qs[t] = g_q[(b*Sc + qi)*Dc + h*64 + t];
    __syncthreads();
    const float* kr = g_k + (b*Sc + t)*Dc + h*64;
    float s = 0.f;
    #pragma unroll
    for (int d = 0; d < 64; d++) s += qs[d]*kr[d];
    s = s*0.125f + (1.0f - mask[b*Sc + t])*NEGBIG;
    sc[t] = s; __syncthreads();
    float m = -1e30f;
    for (int j = 0; j < 64; j++) m = fmaxf(m, sc[j]);
    ps[t] = expf(sc[t] - m);
    __syncthreads();
    float ssum = 0.f, o = 0.f;
    for (int j = 0; j < 64; j++) {
        ssum += ps[j];
        o += ps[j]*g_v[(b*Sc + j)*Dc + h*64 + t];
    }
    g_att[(b*Sc + qi)*Dc + h*64 + t] = o / ssum;
}

// ---- decoder 4-row GEMV: out[4,N] = (opt rmsnorm(x))[4,K] @ W[K,N] (+resid, relu)
//      512 threads, 8-way k split, unroll 8. blockIdx.y selects up to 3 (W,out) pairs ----
__global__ __launch_bounds__(512) void gemv4_k(
    const float* __restrict__ x,
    const float* __restrict__ W0, float* __restrict__ out0, int st0,
    const float* __restrict__ W1, float* __restrict__ out1, int st1,
    const float* __restrict__ W2, float* __restrict__ out2, int st2,
    int K, int kshift, int N,
    const float* __restrict__ lnw,
    const float* __restrict__ resid, int relu) {
    __shared__ float xs[4*2048];
    __shared__ float red2[4][128];
    __shared__ float rscale[4];
    __shared__ float redacc[512*4];
    int tid = threadIdx.x;
    const float* W = W0; float* out = out0; int outStride = st0;
    if (blockIdx.y == 1) { W = W1; out = out1; outStride = st1; }
    else if (blockIdx.y == 2) { W = W2; out = out2; outStride = st2; }
    for (int i = tid; i < 4*K; i += 512) xs[i] = x[i];
    __syncthreads();
    if (lnw) {
        int rb = tid >> 7, rt = tid & 127;
        float p = 0.f;
        for (int k = rt; k < K; k += 128) { float v = xs[rb*K + k]; p += v*v; }
        red2[rb][rt] = p; __syncthreads();
        #pragma unroll
        for (int off = 64; off > 0; off >>= 1) {
            if (rt < off) red2[rb][rt] += red2[rb][rt + off];
            __syncthreads();
        }
        if (tid < 4) rscale[tid] = rsqrtf(red2[tid][0] / (float)K + 1e-6f);
        __syncthreads();
        for (int i = tid; i < 4*K; i += 512) {
            int b = i >> kshift, k = i & (K - 1);
            xs[i] *= rscale[b]*lnw[k];
        }
        __syncthreads();
    }
    int c = tid & 63, ks = tid >> 6;   // ks in 0..7
    int n = blockIdx.x*64 + c;
    float a0 = 0.f, a1 = 0.f, a2 = 0.f, a3 = 0.f;
    #pragma unroll 8
    for (int k = ks; k < K; k += 8) {
        float w = W[k*N + n];
        a0 += xs[k]*w;
        a1 += xs[K + k]*w;
        a2 += xs[2*K + k]*w;
        a3 += xs[3*K + k]*w;
    }
    redacc[tid*4 + 0] = a0; redacc[tid*4 + 1] = a1;
    redacc[tid*4 + 2] = a2; redacc[tid*4 + 3] = a3;
    __syncthreads();
    if (ks == 0) {
        float vb[4] = {0.f, 0.f, 0.f, 0.f};
        #pragma unroll
        for (int s2 = 0; s2 < 8; s2++) {
            int t2 = s2*64 + c;
            vb[0] += redacc[t2*4 + 0]; vb[1] += redacc[t2*4 + 1];
            vb[2] += redacc[t2*4 + 2]; vb[3] += redacc[t2*4 + 3];
        }
        #pragma unroll
        for (int b = 0; b < 4; b++) {
            float v = vb[b];
            if (resid) v += resid[b*Dc + n];  // residual always stride D
            if (relu) v = fmaxf(v, 0.f);
            out[b*outStride + n] = v;
        }
    }
}

// ---- decoder self-attention (KV cache, positions 0..p), block per (b,h), 64 threads ----
__global__ void decsattn_k(int l, int p) {
    int b = blockIdx.x >> 3, h = blockIdx.x & 7;
    int t = threadIdx.x;  // 64
    __shared__ float qs[64], sc[Tc], ps[Tc];
    qs[t] = g_q4[b*Dc + h*64 + t];
    __syncthreads();
    int nk = p + 1;
    const float* sK = g_sK + l*Bc*Tc*Dc;
    const float* sV = g_sV + l*Bc*Tc*Dc;
    if (t < nk) {
        const float* kr = sK + (b*Tc + t)*Dc + h*64;
        float s = 0.f;
        #pragma unroll
        for (int d = 0; d < 64; d++) s += qs[d]*kr[d];
        sc[t] = s*0.125f;
    }
    __syncthreads();
    float m = -1e30f;
    for (int j = 0; j < nk; j++) m = fmaxf(m, sc[j]);
    if (t < nk) ps[t] = expf(sc[t] - m);
    __syncthreads();
    float ssum = 0.f, o = 0.f;
    for (int j = 0; j < nk; j++) {
        ssum += ps[j];
        o += ps[j]*sV[(b*Tc + j)*Dc + h*64 + t];
    }
    g_a4[b*Dc + h*64 + t] = o / ssum;
}

// ---- decoder cross-attention over S=64 keys (precomputed), block per (b,h) ----
__global__ void deccattn_k(int l, const float* __restrict__ mask) {
    int b = blockIdx.x >> 3, h = blockIdx.x & 7;
    int t = threadIdx.x;  // 64
    __shared__ float qs[64], sc[64], ps[64];
    qs[t] = g_q4[b*Dc + h*64 + t];
    __syncthreads();
    const float* cK = g_cK + l*Bc*Sc*Dc;
    const float* cV = g_cV + l*Bc*Sc*Dc;
    const float* kr = cK + (b*Sc + t)*Dc + h*64;
    float s = 0.f;
    #pragma unroll
    for (int d = 0; d < 64; d++) s += qs[d]*kr[d];
    sc[t] = s*0.125f + (1.0f - mask[b*Sc + t])*NEGBIG;
    __syncthreads();
    float m = -1e30f;
    for (int j = 0; j < 64; j++) m = fmaxf(m, sc[j]);
    ps[t] = expf(sc[t] - m);
    __syncthreads();
    float ssum = 0.f, o = 0.f;
    for (int j = 0; j < 64; j++) {
        ssum += ps[j];
        o += ps[j]*cV[(b*Sc + j)*Dc + h*64 + t];
    }
    g_a4[b*Dc + h*64 + t] = o / ssum;
}

// ---- lm head with fused final rmsnorm: logits[4,V] = rmsnorm(xd)[4,D] @ lm[D,V] ----
__global__ __launch_bounds__(256) void lmhead_k(const float* __restrict__ lm,
                                                const float* __restrict__ lnf) {
    __shared__ float hs4[4*Dc];
    __shared__ float red[4][64];
    __shared__ float rscale[4];
    int tid = threadIdx.x;
    // fused rmsnorm of g_xd (4 rows of 512)
    {
        int rb = tid >> 6, rt = tid & 63;
        float p = 0.f;
        for (int k = rt; k < Dc; k += 64) { float v = g_xd[rb*Dc + k]; p += v*v; }
        red[rb][rt] = p; __syncthreads();
        #pragma unroll
        for (int off = 32; off > 0; off >>= 1) {
            if (rt < off) red[rb][rt] += red[rb][rt + off];
            __syncthreads();
        }
        if (tid < 4) rscale[tid] = rsqrtf(red[tid][0] / (float)Dc + 1e-6f);
        __syncthreads();
        for (int i = tid; i < 4*Dc; i += 256)
            hs4[i] = g_xd[i] * rscale[i >> 9] * lnf[i & (Dc-1)];
        __syncthreads();
    }
    int v = blockIdx.x*256 + tid;
    if (v < Vc) {
        float a0 = 0.f, a1 = 0.f, a2 = 0.f, a3 = 0.f;
        #pragma unroll 8
        for (int d = 0; d < Dc; d++) {
            float w = lm[d*Vc + v];
            a0 += hs4[d]*w; a1 += hs4[Dc + d]*w;
            a2 += hs4[2*Dc + d]*w; a3 += hs4[3*Dc + d]*w;
        }
        g_logits[v] = a0; g_logits[Vc + v] = a1;
        g_logits[2*Vc + v] = a2; g_logits[3*Vc + v] = a3;
    }
}

// ---- softmax over V + argmax, writes prob_history row + pad-flag ----
__global__ __launch_bounds__(512) void softmax_k(float* __restrict__ out, int step, int flagOK) {
    int b = blockIdx.x, tid = threadIdx.x;  // 512 threads
    __shared__ float sm[512]; __shared__ int si[512]; __shared__ float bsum[512];
    const float* lg = g_logits + b*Vc;
    float m = -1e30f; int mi = 0;
    for (int v = tid; v < Vc; v += 512) {
        float x = lg[v];
        if (x > m) { m = x; mi = v; }
    }
    sm[tid] = m; si[tid] = mi; __syncthreads();
    #pragma unroll
    for (int off = 256; off > 0; off >>= 1) {
        if (tid < off) {
            float m2 = sm[tid + off]; int i2 = si[tid + off];
            if (m2 > sm[tid] || (m2 == sm[tid] && i2 < si[tid])) { sm[tid] = m2; si[tid] = i2; }
        }
        __syncthreads();
    }
    float gm = sm[0]; int gi = si[0];
    float* po = out + ((size_t)b*Tc + step)*Vc;
    float p = 0.f;
    for (int v = tid; v < Vc; v += 512) {
        float e = expf(lg[v] - gm);
        po[v] = e;            // store unnormalized; scaled below by same thread
        p += e;
    }
    bsum[tid] = p; __syncthreads();
    #pragma unroll
    for (int off = 256; off > 0; off >>= 1) {
        if (tid < off) bsum[tid] += bsum[tid + off];
        __syncthreads();
    }
    float inv = 1.0f / bsum[0];
    for (int v = tid; v < Vc; v += 512) po[v] *= inv;   // same-thread RMW, no race
    if (tid == 0 && flagOK)
        out[(size_t)Bc*Tc*Vc + b*Tc + step] = (gi == 0) ? 1.0f : 0.0f;
}

// ---- soft embedding: partial sums of probs @ emb over v-chunks (deterministic) ----
__global__ void softemb_k(const float* __restrict__ out, int step,
                          const float* __restrict__ emb) {
    int d = blockIdx.x*128 + threadIdx.x;  // grid.x = 4
    int cz = blockIdx.y;                    // 64 chunks of 502 v's
    int v0 = cz*502, v1 = v0 + 502;
    const float* p0 = out + ((size_t)0*Tc + step)*Vc;
    const float* p1 = out + ((size_t)1*Tc + step)*Vc;
    const float* p2 = out + ((size_t)2*Tc + step)*Vc;
    const float* p3 = out + ((size_t)3*Tc + step)*Vc;
    float a0 = 0.f, a1 = 0.f, a2 = 0.f, a3 = 0.f;
    #pragma unroll 4
    for (int v = v0; v < v1; v++) {
        float e = emb[(size_t)v*Dc + d];
        a0 += p0[v]*e; a1 += p1[v]*e; a2 += p2[v]*e; a3 += p3[v]*e;
    }
    g_part[(cz*Bc + 0)*Dc + d] = a0;
    g_part[(cz*Bc + 1)*Dc + d] = a1;
    g_part[(cz*Bc + 2)*Dc + d] = a2;
    g_part[(cz*Bc + 3)*Dc + d] = a3;
}

__global__ void reduce_k() {
    int idx = blockIdx.x*256 + threadIdx.x;  // 2048 = B*D
    float s = 0.f;
    #pragma unroll 8
    for (int c = 0; c < NCH; c++) s += g_part[c*Bc*Dc + idx];
    g_xd[idx] = s;
}

// ======================= host =======================
extern "C" void kernel_launch(void* const* d_in, const int* in_sizes, int n_in,
                              void* d_out, int out_size) {
    const int*   ids     = (const int*)d_in[0];
    const float* mask    = (const float*)d_in[1];
    const float* emb     = (const float*)d_in[2];
    const float* enc_wq  = (const float*)d_in[3];
    const float* enc_wk  = (const float*)d_in[4];
    const float* enc_wv  = (const float*)d_in[5];
    const float* enc_wo  = (const float*)d_in[6];
    const float* enc_ln1 = (const float*)d_in[7];
    const float* enc_w1  = (const float*)d_in[8];
    const float* enc_w2  = (const float*)d_in[9];
    const float* enc_ln2 = (const float*)d_in[10];
    const float* enc_lnf = (const float*)d_in[11];
    const float* dec_sq  = (const float*)d_in[12];
    const float* dec_sk  = (const float*)d_in[13];
    const float* dec_sv  = (const float*)d_in[14];
    const float* dec_so  = (const float*)d_in[15];
    const float* dec_ln1 = (const float*)d_in[16];
    const float* dec_cq  = (const float*)d_in[17];
    const float* dec_ck  = (const float*)d_in[18];
    const float* dec_cv  = (const float*)d_in[19];
    const float* dec_co  = (const float*)d_in[20];
    const float* dec_ln2 = (const float*)d_in[21];
    const float* dec_w1  = (const float*)d_in[22];
    const float* dec_w2  = (const float*)d_in[23];
    const float* dec_ln3 = (const float*)d_in[24];
    const float* dec_lnf = (const float*)d_in[25];
    const float* lm      = (const float*)d_in[26];
    float* out = (float*)d_out;

    void* vp;
    cudaGetSymbolAddress(&vp, g_x);   float* px   = (float*)vp;
    cudaGetSymbolAddress(&vp, g_h);   float* ph   = (float*)vp;
    cudaGetSymbolAddress(&vp, g_q);   float* pq   = (float*)vp;
    cudaGetSymbolAddress(&vp, g_k);   float* pk   = (float*)vp;
    cudaGetSymbolAddress(&vp, g_v);   float* pv   = (float*)vp;
    cudaGetSymbolAddress(&vp, g_att); float* patt = (float*)vp;
    cudaGetSymbolAddress(&vp, g_ff);  float* pff  = (float*)vp;
    cudaGetSymbolAddress(&vp, g_hs);  float* phs  = (float*)vp;
    cudaGetSymbolAddress(&vp, g_cK);  float* pcK  = (float*)vp;
    cudaGetSymbolAddress(&vp, g_cV);  float* pcV  = (float*)vp;
    cudaGetSymbolAddress(&vp, g_sK);  float* psK  = (float*)vp;
    cudaGetSymbolAddress(&vp, g_sV);  float* psV  = (float*)vp;
    cudaGetSymbolAddress(&vp, g_xd);  float* pxd  = (float*)vp;
    cudaGetSymbolAddress(&vp, g_q4);  float* pq4  = (float*)vp;
    cudaGetSymbolAddress(&vp, g_a4);  float* pa4  = (float*)vp;
    cudaGetSymbolAddress(&vp, g_f4);  float* pf4  = (float*)vp;

    const int M = Bc*Sc;  // 256

    // ---------- encoder ----------
    embed_k<<<M + Bc, 256>>>(ids, emb);
    for (int l = 0; l < Lc; l++) {
        rmsnorm_k<<<M, 256>>>(px, ph, enc_ln1 + l*Dc);
        gemm_k<<<dim3(8, 4, 3), 256>>>(ph,
            enc_wq + l*Dc*Dc, pq, enc_wk + l*Dc*Dc, pk, enc_wv + l*Dc*Dc, pv,
            nullptr, nullptr, M, Dc, Dc, nullptr, 0);
        encattn_k<<<Bc*Hc*Sc, 64>>>(mask);
        gemm_k<<<dim3(8, 4, 1), 256>>>(patt,
            enc_wo + l*Dc*Dc, px, nullptr, nullptr, nullptr, nullptr, nullptr, nullptr,
            M, Dc, Dc, px, 0);
        rmsnorm_k<<<M, 256>>>(px, ph, enc_ln2 + l*Dc);
        gemm_k<<<dim3(32, 4, 1), 256>>>(ph,
            enc_w1 + l*Dc*Fc, pff, nullptr, nullptr, nullptr, nullptr, nullptr, nullptr,
            M, Fc, Dc, nullptr, 1);
        gemm_k<<<dim3(8, 4, 1), 256>>>(pff,
            enc_w2 + l*Fc*Dc, px, nullptr, nullptr, nullptr, nullptr, nullptr, nullptr,
            M, Dc, Fc, px, 0);
    }
    rmsnorm_k<<<M, 256>>>(px, phs, enc_lnf);

    // cross-attention K/V precompute for both layers in one launch
    gemm_k<<<dim3(8, 4, 4), 256>>>(phs,
        dec_ck,           pcK,
        dec_cv,           pcV,
        dec_ck + Dc*Dc,   pcK + Bc*Sc*Dc,
        dec_cv + Dc*Dc,   pcV + Bc*Sc*Dc,
        M, Dc, Dc, nullptr, 0);

    // ---------- decoder (incremental; exactly equivalent to full re-run) ----------
    int flagOK = (out_size >= Bc*Tc*Vc + Bc*Tc) ? 1 : 0;

    for (int p = 0; p < Tc; p++) {
        for (int l = 0; l < Lc; l++) {
            const float* ln1 = dec_ln1 + l*Dc;
            // fused self-attn q,k,v for the new token (k/v written straight into cache at pos p)
            gemv4_k<<<dim3(8, 3), 512>>>(pxd,
                dec_sq + l*Dc*Dc, pq4, Dc,
                dec_sk + l*Dc*Dc, psK + l*Bc*Tc*Dc + p*Dc, Tc*Dc,
                dec_sv + l*Dc*Dc, psV + l*Bc*Tc*Dc + p*Dc, Tc*Dc,
                Dc, 9, Dc, ln1, nullptr, 0);
            decsattn_k<<<Bc*Hc, 64>>>(l, p);
            gemv4_k<<<dim3(8, 1), 512>>>(pa4,
                dec_so + l*Dc*Dc, pxd, Dc,
                nullptr, nullptr, 0, nullptr, nullptr, 0,
                Dc, 9, Dc, nullptr, pxd, 0);
            // cross attention
            gemv4_k<<<dim3(8, 1), 512>>>(pxd,
                dec_cq + l*Dc*Dc, pq4, Dc,
                nullptr, nullptr, 0, nullptr, nullptr, 0,
                Dc, 9, Dc, dec_ln2 + l*Dc, nullptr, 0);
            deccattn_k<<<Bc*Hc, 64>>>(l, mask);
            gemv4_k<<<dim3(8, 1), 512>>>(pa4,
                dec_co + l*Dc*Dc, pxd, Dc,
                nullptr, nullptr, 0, nullptr, nullptr, 0,
                Dc, 9, Dc, nullptr, pxd, 0);
            // ffn
            gemv4_k<<<dim3(32, 1), 512>>>(pxd,
                dec_w1 + l*Dc*Fc, pf4, Fc,
                nullptr, nullptr, 0, nullptr, nullptr, 0,
                Dc, 9, Fc, dec_ln3 + l*Dc, nullptr, 1);
            gemv4_k<<<dim3(8, 1), 512>>>(pf4,
                dec_w2 + l*Fc*Dc, pxd, Dc,
                nullptr, nullptr, 0, nullptr, nullptr, 0,
                Fc, 11, Dc, nullptr, pxd, 0);
        }
        lmhead_k<<<(Vc + 255)/256, 256>>>(lm, dec_lnf);
        softmax_k<<<Bc, 512>>>(out, p, flagOK);
        softemb_k<<<dim3(4, NCH), 128>>>(out, p, emb);
        reduce_k<<<8, 256>>>();
    }
}

// round 6
// speedup vs baseline: 1.6828x; 1.0771x over previous
#include <cuda_runtime.h>
#include <math.h>

// ---- problem constants ----
constexpr int Bc = 4;
constexpr int Sc = 64;
constexpr int Dc = 512;
constexpr int Hc = 8;
constexpr int Fc = 2048;
constexpr int Lc = 2;
constexpr int Vc = 32128;
constexpr int Tc = 16;
constexpr int NB = 148;          // megakernel blocks (== SM count, all co-resident)
constexpr int NCHV = 251;        // soft-emb v-chunks (V = 251*128)
#define NEGBIG (-1e9f)

// ---- scratch (static device globals; no allocation allowed) ----
__device__ float g_x[Bc*Sc*Dc];
__device__ float g_h[Bc*Sc*Dc];
__device__ float g_q[Bc*Sc*Dc];
__device__ float g_k[Bc*Sc*Dc];
__device__ float g_v[Bc*Sc*Dc];
__device__ float g_att[Bc*Sc*Dc];
__device__ float g_ff[Bc*Sc*Fc];
__device__ float g_hs[Bc*Sc*Dc];
__device__ float g_cK[Lc*Bc*Sc*Dc];
__device__ float g_cV[Lc*Bc*Sc*Dc];
__device__ float g_sK[Lc*Bc*Tc*Dc];
__device__ float g_sV[Lc*Bc*Tc*Dc];
__device__ float g_xdA[Bc*Dc];
__device__ float g_xdB[Bc*Dc];
__device__ float g_a4[Bc*Dc];
__device__ float g_f4[Bc*Fc];
__device__ float g_gp1[8*4*2048];     // gemv partials buffer 1
__device__ float g_gp2[32*4*512];     // gemv partials buffer 2 (supports KC=32, C=512)
__device__ float g_logits[Bc*Vc];
__device__ float g_pmax[4*1024];
__device__ int   g_pidx[4*1024];
__device__ float g_sep[NCHV*4*512];   // soft-emb chunk partials (~2MB)
__device__ float g_psum[NCHV*4];

// ---- software grid barrier (all NB blocks co-resident; sense-reversing) ----
__device__ unsigned int g_barArrive = 0;
__device__ unsigned int g_barGen = 0;

__device__ __forceinline__ void gridbar() {
    __syncthreads();
    if (threadIdx.x == 0) {
        unsigned int gen = ((volatile unsigned int*)&g_barGen)[0];
        __threadfence();
        unsigned int a = atomicAdd(&g_barArrive, 1u);
        if (a == NB - 1) {
            g_barArrive = 0;
            __threadfence();
            atomicAdd(&g_barGen, 1u);
        } else {
            while (((volatile unsigned int*)&g_barGen)[0] == gen) { __nanosleep(64); }
        }
        __threadfence();
    }
    __syncthreads();
}

// =================== encoder kernels (as round 4, passing) ===================
__global__ void embed_k(const int* __restrict__ ids, const float* __restrict__ emb) {
    int bs = blockIdx.x, tid = threadIdx.x;
    int tok = ids[bs];
    for (int d = tid; d < Dc; d += 256) g_x[bs*Dc + d] = emb[tok*Dc + d];
}

__global__ void rmsnorm_k(const float* __restrict__ src, float* __restrict__ dst,
                          const float* __restrict__ w) {
    int row = blockIdx.x, tid = threadIdx.x;
    __shared__ float red[256];
    const float* s = src + row*Dc;
    float p = 0.f;
    for (int d = tid; d < Dc; d += 256) { float v = s[d]; p += v*v; }
    red[tid] = p; __syncthreads();
    for (int off = 128; off > 0; off >>= 1) {
        if (tid < off) red[tid] += red[tid + off];
        __syncthreads();
    }
    float scale = rsqrtf(red[0] / (float)Dc + 1e-6f);
    for (int d = tid; d < Dc; d += 256) dst[row*Dc + d] = s[d] * scale * w[d];
}

__global__ __launch_bounds__(256) void gemm_k(
    const float* __restrict__ A,
    const float* __restrict__ W0, float* __restrict__ C0,
    const float* __restrict__ W1, float* __restrict__ C1,
    const float* __restrict__ W2, float* __restrict__ C2,
    const float* __restrict__ W3, float* __restrict__ C3,
    int M, int N, int K,
    const float* __restrict__ resid, int relu) {
    __shared__ float As[2][16][65];
    __shared__ float Bs[2][16][65];
    int bm = blockIdx.y*64, bn = blockIdx.x*64;
    int tid = threadIdx.x;
    int tr = tid >> 4, tc = tid & 15;
    const float* W = W0; float* C = C0;
    if (blockIdx.z == 1) { W = W1; C = C1; }
    else if (blockIdx.z == 2) { W = W2; C = C2; }
    else if (blockIdx.z == 3) { W = W3; C = C3; }

    float ra[4], rb[4];
    #pragma unroll
    for (int j = 0; j < 4; j++) { int i = tid + j*256; ra[j] = A[(bm + (i>>4))*K + (i&15)]; }
    #pragma unroll
    for (int j = 0; j < 4; j++) { int i = tid + j*256; rb[j] = W[(i>>6)*N + bn + (i&63)]; }
    #pragma unroll
    for (int j = 0; j < 4; j++) { int i = tid + j*256; As[0][i&15][i>>4] = ra[j]; }
    #pragma unroll
    for (int j = 0; j < 4; j++) { int i = tid + j*256; Bs[0][i>>6][i&63] = rb[j]; }
    __syncthreads();

    float acc[4][4] = {};
    int buf = 0;
    for (int k0 = 16; k0 <= K; k0 += 16) {
        if (k0 < K) {
            #pragma unroll
            for (int j = 0; j < 4; j++) { int i = tid + j*256; ra[j] = A[(bm + (i>>4))*K + k0 + (i&15)]; }
            #pragma unroll
            for (int j = 0; j < 4; j++) { int i = tid + j*256; rb[j] = W[(k0 + (i>>6))*N + bn + (i&63)]; }
        }
        #pragma unroll
        for (int kk = 0; kk < 16; kk++) {
            float a[4], bv[4];
            #pragma unroll
            for (int i = 0; i < 4; i++) a[i] = As[buf][kk][tr*4 + i];
            #pragma unroll
            for (int j = 0; j < 4; j++) bv[j] = Bs[buf][kk][tc*4 + j];
            #pragma unroll
            for (int i = 0; i < 4; i++)
                #pragma unroll
                for (int j = 0; j < 4; j++) acc[i][j] += a[i]*bv[j];
        }
        if (k0 < K) {
            #pragma unroll
            for (int j = 0; j < 4; j++) { int i = tid + j*256; As[buf^1][i&15][i>>4] = ra[j]; }
            #pragma unroll
            for (int j = 0; j < 4; j++) { int i = tid + j*256; Bs[buf^1][i>>6][i&63] = rb[j]; }
        }
        __syncthreads();
        buf ^= 1;
    }
    #pragma unroll
    for (int i = 0; i < 4; i++)
        #pragma unroll
        for (int j = 0; j < 4; j++) {
            int r = bm + tr*4 + i, c = bn + tc*4 + j;
            float v = acc[i][j];
            if (resid) v += resid[r*N + c];
            if (relu) v = fmaxf(v, 0.f);
            C[r*N + c] = v;
        }
}

__global__ void encattn_k(const float* __restrict__ mask) {
    int blk = blockIdx.x;
    int qi = blk % Sc; int h = (blk / Sc) % Hc; int b = blk / (Sc*Hc);
    int t = threadIdx.x;  // 64
    __shared__ float qs[64], sc[64], ps[64];
    qs[t] = g_q[(b*Sc + qi)*Dc + h*64 + t];
    __syncthreads();
    const float* kr = g_k + (b*Sc + t)*Dc + h*64;
    float s = 0.f;
    #pragma unroll
    for (int d = 0; d < 64; d++) s += qs[d]*kr[d];
    s = s*0.125f + (1.0f - mask[b*Sc + t])*NEGBIG;
    sc[t] = s; __syncthreads();
    float m = -1e30f;
    for (int j = 0; j < 64; j++) m = fmaxf(m, sc[j]);
    ps[t] = expf(sc[t] - m);
    __syncthreads();
    float ssum = 0.f, o = 0.f;
    for (int j = 0; j < 64; j++) {
        ssum += ps[j];
        o += ps[j]*g_v[(b*Sc + j)*Dc + h*64 + t];
    }
    g_att[(b*Sc + qi)*Dc + h*64 + t] = o / ssum;
}

// =================== decode megakernel helpers ===================

// rms-normalize the 4xK block in smem in place (K power of 2)
__device__ __forceinline__ void rms_apply(float* xn, int K, int kshift,
                                          const float* __restrict__ lnw,
                                          float* red, float* rsc) {
    int rb = threadIdx.x >> 6, rt = threadIdx.x & 63;
    float p = 0.f;
    for (int k = rt; k < K; k += 64) { float v = xn[rb*K + k]; p += v*v; }
    red[rb*64 + rt] = p; __syncthreads();
    #pragma unroll
    for (int off = 32; off > 0; off >>= 1) {
        if (rt < off) red[rb*64 + rt] += red[rb*64 + rt + off];
        __syncthreads();
    }
    if (threadIdx.x < 4) rsc[threadIdx.x] = rsqrtf(red[threadIdx.x*64] / (float)K + 1e-6f);
    __syncthreads();
    for (int i = threadIdx.x; i < 4*K; i += 256) xn[i] *= rsc[i >> kshift] * lnw[i & (K-1)];
    __syncthreads();
}

// partial GEMV: tasks = (C/32 col-tiles) x KC k-chunks, one warp per task
__device__ __forceinline__ void gemv_part(const float* __restrict__ W, const float* xn,
                                          int K, int C, int KC, int ck,
                                          float* __restrict__ gp, int gs) {
    int warp = threadIdx.x >> 5, lane = threadIdx.x & 31;
    int ntiles = C >> 5;
    int ntasks = ntiles * KC;
    for (int tt = blockIdx.x + warp*NB; tt < ntasks; tt += NB*8) {
        int tile = tt % ntiles, kc = tt / ntiles;
        int n = (tile << 5) + lane;
        int k0 = kc*ck, k1 = k0 + ck;
        float a0 = 0.f, a1 = 0.f, a2 = 0.f, a3 = 0.f;
        #pragma unroll 4
        for (int k = k0; k < k1; k++) {
            float w = W[k*C + n];
            a0 += xn[k]*w; a1 += xn[K+k]*w; a2 += xn[2*K+k]*w; a3 += xn[3*K+k]*w;
        }
        gp[(kc*4+0)*gs + n] = a0;
        gp[(kc*4+1)*gs + n] = a1;
        gp[(kc*4+2)*gs + n] = a2;
        gp[(kc*4+3)*gs + n] = a3;
    }
}

// fused q/k/v partials (virtual C=1536: q|k|v each 512 cols), KC=8
__device__ __forceinline__ void qkv_part(const float* __restrict__ Wq,
                                         const float* __restrict__ Wk,
                                         const float* __restrict__ Wv,
                                         const float* xn) {
    int warp = threadIdx.x >> 5, lane = threadIdx.x & 31;
    for (int tt = blockIdx.x + warp*NB; tt < 48*8; tt += NB*8) {
        int tile = tt % 48, kc = tt / 48;
        const float* W = (tile < 16) ? Wq : (tile < 32 ? Wk : Wv);
        int nloc = ((tile & 15) << 5) + lane;
        int k0 = kc*64;
        float a0 = 0.f, a1 = 0.f, a2 = 0.f, a3 = 0.f;
        #pragma unroll 4
        for (int k = k0; k < k0+64; k++) {
            float w = W[k*512 + nloc];
            a0 += xn[k]*w; a1 += xn[512+k]*w; a2 += xn[1024+k]*w; a3 += xn[1536+k]*w;
        }
        int n = tile*32 + lane;
        g_gp1[(kc*4+0)*2048 + n] = a0;
        g_gp1[(kc*4+1)*2048 + n] = a1;
        g_gp1[(kc*4+2)*2048 + n] = a2;
        g_gp1[(kc*4+3)*2048 + n] = a3;
    }
}

// combine gp partials + residual(xdr) -> smem xn AND xdw (redundant same-value writes, benign)
__device__ __forceinline__ void comb_resid_smem(float* xn, const float* __restrict__ gp,
                                                const float* __restrict__ xdr,
                                                float* __restrict__ xdw) {
    for (int i = threadIdx.x; i < 2048; i += 256) {
        int b = i >> 9, k = i & 511;
        float s = xdr[i];
        #pragma unroll
        for (int kc = 0; kc < 8; kc++) s += gp[(kc*4+b)*2048 + k];
        xn[i] = s; xdw[i] = s;
    }
    __syncthreads();
}

// self-attention over KV cache (combines q/k/v partials, writes cache at pos p)
__device__ __forceinline__ void self_attn(int l, int p, float* sq, float* ssc, float* sps) {
    int blk = blockIdx.x, b = blk >> 3, h = blk & 7, t = threadIdx.x;
    bool act = (blk < 32) && (t < 64);
    int nk = p + 1;
    if (act) {
        float qv = 0.f, kn = 0.f, vn = 0.f;
        int col = h*64 + t;
        #pragma unroll
        for (int kc = 0; kc < 8; kc++) {
            const float* gp = g_gp1 + (kc*4+b)*2048;
            qv += gp[col]; kn += gp[512 + col]; vn += gp[1024 + col];
        }
        sq[t] = qv;
        g_sK[((l*Bc + b)*Tc + p)*Dc + col] = kn;
        g_sV[((l*Bc + b)*Tc + p)*Dc + col] = vn;
    }
    __syncthreads();
    if (act && t < nk) {
        const float* kr = g_sK + ((l*Bc + b)*Tc + t)*Dc + h*64;
        float s = 0.f;
        #pragma unroll
        for (int d = 0; d < 64; d++) s += sq[d]*kr[d];
        ssc[t] = s*0.125f;
    }
    __syncthreads();
    if (act) {
        float m = -1e30f;
        for (int j = 0; j < nk; j++) m = fmaxf(m, ssc[j]);
        if (t < nk) sps[t] = expf(ssc[t] - m);
    }
    __syncthreads();
    if (act) {
        float ssum = 0.f, o = 0.f;
        for (int j = 0; j < nk; j++) {
            ssum += sps[j];
            o += sps[j]*g_sV[((l*Bc + b)*Tc + j)*Dc + h*64 + t];
        }
        g_a4[b*512 + h*64 + t] = o/ssum;
    }
}

__device__ __forceinline__ void cross_attn(int l, const float* __restrict__ mask,
                                           float* sq, float* ssc, float* sps) {
    int blk = blockIdx.x, b = blk >> 3, h = blk & 7, t = threadIdx.x;
    bool act = (blk < 32) && (t < 64);
    if (act) {
        float qv = 0.f;
        int col = h*64 + t;
        #pragma unroll
        for (int kc = 0; kc < 8; kc++) qv += g_gp1[(kc*4+b)*2048 + col];
        sq[t] = qv;
    }
    __syncthreads();
    if (act) {
        const float* kr = g_cK + ((l*Bc + b)*Sc + t)*Dc + h*64;
        float s = 0.f;
        #pragma unroll
        for (int d = 0; d < 64; d++) s += sq[d]*kr[d];
        ssc[t] = s*0.125f + (1.0f - mask[b*Sc + t])*NEGBIG;
    }
    __syncthreads();
    if (act) {
        float m = -1e30f;
        for (int j = 0; j < 64; j++) m = fmaxf(m, ssc[j]);
        sps[t] = expf(ssc[t] - m);
    }
    __syncthreads();
    if (act) {
        float ssum = 0.f, o = 0.f;
        for (int j = 0; j < 64; j++) {
            ssum += sps[j];
            o += sps[j]*g_cV[((l*Bc + b)*Sc + j)*Dc + h*64 + t];
        }
        g_a4[b*512 + h*64 + t] = o/ssum;
    }
}

// lm head: logits + per-task (max, argmax) partials. 1004 warp tasks of 32 cols.
__device__ __forceinline__ void lm_part(const float* __restrict__ lm, const float* xn) {
    int warp = threadIdx.x >> 5, lane = threadIdx.x & 31;
    const unsigned full = 0xffffffffu;
    for (int tt = blockIdx.x + warp*NB; tt < 1004; tt += NB*8) {
        int n = tt*32 + lane;
        float a0 = 0.f, a1 = 0.f, a2 = 0.f, a3 = 0.f;
        #pragma unroll 4
        for (int k = 0; k < 512; k++) {
            float w = lm[k*Vc + n];
            a0 += xn[k]*w; a1 += xn[512+k]*w; a2 += xn[1024+k]*w; a3 += xn[1536+k]*w;
        }
        g_logits[0*Vc + n] = a0; g_logits[1*Vc + n] = a1;
        g_logits[2*Vc + n] = a2; g_logits[3*Vc + n] = a3;
        float vals[4] = {a0, a1, a2, a3};
        #pragma unroll
        for (int b = 0; b < 4; b++) {
            float mv = vals[b]; int mi = n;
            #pragma unroll
            for (int off = 16; off > 0; off >>= 1) {
                float v2 = __shfl_down_sync(full, mv, off);
                int   i2 = __shfl_down_sync(full, mi, off);
                if (v2 > mv || (v2 == mv && i2 < mi)) { mv = v2; mi = i2; }
            }
            if (lane == 0) { g_pmax[b*1024 + tt] = mv; g_pidx[b*1024 + tt] = mi; }
        }
    }
}

// softmax partials + soft-embedding chunk partials
__device__ __forceinline__ void se_stage(float* __restrict__ out, int step,
                                         const float* __restrict__ emb,
                                         float* red, float* gmax, float* ev) {
    int tid = threadIdx.x;
    // redundant global max per batch
    #pragma unroll
    for (int b = 0; b < 4; b++) {
        float m = -1e30f;
        for (int t2 = tid; t2 < 1004; t2 += 256) m = fmaxf(m, g_pmax[b*1024 + t2]);
        red[tid] = m; __syncthreads();
        #pragma unroll
        for (int off = 128; off > 0; off >>= 1) {
            if (tid < off) red[tid] = fmaxf(red[tid], red[tid + off]);
            __syncthreads();
        }
        if (tid == 0) gmax[b] = red[0];
        __syncthreads();
    }
    for (int ch = blockIdx.x; ch < NCHV; ch += NB) {
        int v0 = ch*128;
        if (tid < 128) {
            int v = v0 + tid;
            #pragma unroll
            for (int b = 0; b < 4; b++) {
                float e = expf(g_logits[b*Vc + v] - gmax[b]);
                ev[b*128 + tid] = e;
                out[((size_t)b*Tc + step)*Vc + v] = e;   // unnormalized; FIN scales
            }
        }
        __syncthreads();
        int d0 = tid, d1 = tid + 256;
        float a00=0,a01=0,a02=0,a03=0,a10=0,a11=0,a12=0,a13=0;
        for (int v = 0; v < 128; v++) {
            float w0 = emb[(size_t)(v0+v)*512 + d0];
            float w1 = emb[(size_t)(v0+v)*512 + d1];
            float e0 = ev[v], e1 = ev[128+v], e2 = ev[256+v], e3 = ev[384+v];
            a00 += e0*w0; a01 += e1*w0; a02 += e2*w0; a03 += e3*w0;
            a10 += e0*w1; a11 += e1*w1; a12 += e2*w1; a13 += e3*w1;
        }
        g_sep[(ch*4+0)*512 + d0] = a00; g_sep[(ch*4+1)*512 + d0] = a01;
        g_sep[(ch*4+2)*512 + d0] = a02; g_sep[(ch*4+3)*512 + d0] = a03;
        g_sep[(ch*4+0)*512 + d1] = a10; g_sep[(ch*4+1)*512 + d1] = a11;
        g_sep[(ch*4+2)*512 + d1] = a12; g_sep[(ch*4+3)*512 + d1] = a13;
        if (tid < 4) {
            float s = 0.f;
            for (int v = 0; v < 128; v++) s += ev[tid*128 + v];
            g_psum[ch*4 + tid] = s;
        }
        __syncthreads();
    }
}

// finalize: normalize probs, next xd, pad flag
__device__ __forceinline__ void fin_stage(float* __restrict__ out, int step, int flagOK,
                                          float* red, float* inv, float* __restrict__ xdw) {
    int tid = threadIdx.x;
    #pragma unroll
    for (int b = 0; b < 4; b++) {
        float s = 0.f;
        for (int c = tid; c < NCHV; c += 256) s += g_psum[c*4 + b];
        red[tid] = s; __syncthreads();
        #pragma unroll
        for (int off = 128; off > 0; off >>= 1) {
            if (tid < off) red[tid] += red[tid + off];
            __syncthreads();
        }
        if (tid == 0) inv[b] = 1.0f / red[0];
        __syncthreads();
    }
    size_t gt = (size_t)blockIdx.x*256 + tid;
    for (size_t i = gt; i < (size_t)4*Vc; i += (size_t)NB*256) {
        int b = (int)(i / Vc); int v = (int)(i % Vc);
        out[((size_t)b*Tc + step)*Vc + v] *= inv[b];
    }
    for (int i = (int)gt; i < 2048; i += NB*256) {
        int b = i >> 9, k = i & 511;
        float s = 0.f;
        #pragma unroll 4
        for (int c = 0; c < NCHV; c++) s += g_sep[(c*4+b)*512 + k];
        xdw[i] = s * inv[b];
    }
    if (blockIdx.x == 0 && tid < 4 && flagOK) {
        int b = tid; float bm = -1e30f; int bi = 0;
        for (int t2 = 0; t2 < 1004; t2++) {
            float v = g_pmax[b*1024 + t2];
            if (v > bm) { bm = v; bi = g_pidx[b*1024 + t2]; }
        }
        out[(size_t)Bc*Tc*Vc + b*Tc + step] = (bi == 0) ? 1.0f : 0.0f;
    }
}

// =================== the decode megakernel ===================
__global__ __launch_bounds__(256) void decode_k(
    const float* __restrict__ mask, const float* __restrict__ emb,
    const float* __restrict__ sqw, const float* __restrict__ skw, const float* __restrict__ svw,
    const float* __restrict__ sow, const float* __restrict__ ln1,
    const float* __restrict__ cqw, const float* __restrict__ cow, const float* __restrict__ ln2,
    const float* __restrict__ w1w, const float* __restrict__ w2w, const float* __restrict__ ln3,
    const float* __restrict__ lnf, const float* __restrict__ lm,
    float* __restrict__ out, int flagOK)
{
    __shared__ float s_xn[4*2048];
    __shared__ float s_red[256];
    __shared__ float s_rsc[4];
    __shared__ float s_q[64], s_sc[64], s_ps[64];
    __shared__ float s_ev[4*128];
    __shared__ float s_gmax[4];
    int tid = threadIdx.x;

    float* xdr = g_xdA;
    float* xdw = g_xdB;

    // init: decoder hidden = pad embedding (row 0) for all 4 batches
    if (blockIdx.x == 0)
        for (int i = tid; i < 2048; i += 256) g_xdA[i] = emb[i & 511];
    gridbar();

    for (int p = 0; p < Tc; p++) {
        for (int l = 0; l < Lc; l++) {
            // --- L1: xn = rmsnorm(xd, ln1); qkv partials -> gp1
            for (int i = tid; i < 2048; i += 256) s_xn[i] = xdr[i];
            __syncthreads();
            rms_apply(s_xn, 512, 9, ln1 + l*512, s_red, s_rsc);
            qkv_part(sqw + l*512*512, skw + l*512*512, svw + l*512*512, s_xn);
            gridbar();
            // --- L2: self attention (combines gp1, writes KV cache @p) -> a4
            self_attn(l, p, s_q, s_sc, s_ps);
            gridbar();
            // --- L3: o-proj partials (x = a4) -> gp2
            for (int i = tid; i < 2048; i += 256) s_xn[i] = g_a4[i];
            __syncthreads();
            gemv_part(sow + l*512*512, s_xn, 512, 512, 8, 64, g_gp2, 2048);
            gridbar();
            // --- L4: xd += o; rms ln2; cq partials -> gp1
            comb_resid_smem(s_xn, g_gp2, xdr, xdw);
            { float* t2 = xdr; xdr = xdw; xdw = t2; }
            rms_apply(s_xn, 512, 9, ln2 + l*512, s_red, s_rsc);
            gemv_part(cqw + l*512*512, s_xn, 512, 512, 8, 64, g_gp1, 2048);
            gridbar();
            // --- L5: cross attention -> a4
            cross_attn(l, mask, s_q, s_sc, s_ps);
            gridbar();
            // --- L6: co-proj partials -> gp2
            for (int i = tid; i < 2048; i += 256) s_xn[i] = g_a4[i];
            __syncthreads();
            gemv_part(cow + l*512*512, s_xn, 512, 512, 8, 64, g_gp2, 2048);
            gridbar();
            // --- L7: xd += co; rms ln3; w1 partials (C=2048) -> gp1
            comb_resid_smem(s_xn, g_gp2, xdr, xdw);
            { float* t2 = xdr; xdr = xdw; xdw = t2; }
            rms_apply(s_xn, 512, 9, ln3 + l*512, s_red, s_rsc);
            gemv_part(w1w + l*512*2048, s_xn, 512, 2048, 8, 64, g_gp1, 2048);
            gridbar();
            // --- L7b: combine + relu -> f4 (distributed)
            for (int i = tid + blockIdx.x*256; i < 8192; i += NB*256) {
                int b = i >> 11, k = i & 2047;
                float s = 0.f;
                #pragma unroll
                for (int kc = 0; kc < 8; kc++) s += g_gp1[(kc*4+b)*2048 + k];
                g_f4[i] = fmaxf(s, 0.f);
            }
            gridbar();
            // --- L8: w2 partials (K=2048, KC=32) -> gp2
            for (int i = tid; i < 8192; i += 256) s_xn[i] = g_f4[i];
            __syncthreads();
            gemv_part(w2w + l*2048*512, s_xn, 2048, 512, 32, 64, g_gp2, 512);
            gridbar();
            // --- L8b: xd += w2 (distributed combine)
            for (int i = tid + blockIdx.x*256; i < 2048; i += NB*256) {
                int b = i >> 9, k = i & 511;
                float s = xdr[i];
                #pragma unroll
                for (int kc = 0; kc < 32; kc++) s += g_gp2[(kc*4+b)*512 + k];
                xdw[i] = s;
            }
            gridbar();
            { float* t2 = xdr; xdr = xdw; xdw = t2; }
        }
        // --- LM: rmsnorm(xd, lnf); lm head -> logits + pmax/pidx
        for (int i = tid; i < 2048; i += 256) s_xn[i] = xdr[i];
        __syncthreads();
        rms_apply(s_xn, 512, 9, lnf, s_red, s_rsc);
        lm_part(lm, s_xn);
        gridbar();
        // --- SE: softmax + soft-embedding partials
        se_stage(out, p, emb, s_red, s_gmax, s_ev);
        gridbar();
        // --- FIN: normalize probs, xd_next, pad flag
        fin_stage(out, p, flagOK, s_red, s_rsc, xdw);
        gridbar();
        { float* t2 = xdr; xdr = xdw; xdw = t2; }
    }
}

// ======================= host =======================
extern "C" void kernel_launch(void* const* d_in, const int* in_sizes, int n_in,
                              void* d_out, int out_size) {
    const int*   ids     = (const int*)d_in[0];
    const float* mask    = (const float*)d_in[1];
    const float* emb     = (const float*)d_in[2];
    const float* enc_wq  = (const float*)d_in[3];
    const float* enc_wk  = (const float*)d_in[4];
    const float* enc_wv  = (const float*)d_in[5];
    const float* enc_wo  = (const float*)d_in[6];
    const float* enc_ln1 = (const float*)d_in[7];
    const float* enc_w1  = (const float*)d_in[8];
    const float* enc_w2  = (const float*)d_in[9];
    const float* enc_ln2 = (const float*)d_in[10];
    const float* enc_lnf = (const float*)d_in[11];
    const float* dec_sq  = (const float*)d_in[12];
    const float* dec_sk  = (const float*)d_in[13];
    const float* dec_sv  = (const float*)d_in[14];
    const float* dec_so  = (const float*)d_in[15];
    const float* dec_ln1 = (const float*)d_in[16];
    const float* dec_cq  = (const float*)d_in[17];
    const float* dec_ck  = (const float*)d_in[18];
    const float* dec_cv  = (const float*)d_in[19];
    const float* dec_co  = (const float*)d_in[20];
    const float* dec_ln2 = (const float*)d_in[21];
    const float* dec_w1  = (const float*)d_in[22];
    const float* dec_w2  = (const float*)d_in[23];
    const float* dec_ln3 = (const float*)d_in[24];
    const float* dec_lnf = (const float*)d_in[25];
    const float* lm      = (const float*)d_in[26];
    float* out = (float*)d_out;

    void* vp;
    cudaGetSymbolAddress(&vp, g_x);   float* px   = (float*)vp;
    cudaGetSymbolAddress(&vp, g_h);   float* ph   = (float*)vp;
    cudaGetSymbolAddress(&vp, g_q);   float* pq   = (float*)vp;
    cudaGetSymbolAddress(&vp, g_k);   float* pk   = (float*)vp;
    cudaGetSymbolAddress(&vp, g_v);   float* pv   = (float*)vp;
    cudaGetSymbolAddress(&vp, g_att); float* patt = (float*)vp;
    cudaGetSymbolAddress(&vp, g_ff);  float* pff  = (float*)vp;
    cudaGetSymbolAddress(&vp, g_hs);  float* phs  = (float*)vp;
    cudaGetSymbolAddress(&vp, g_cK);  float* pcK  = (float*)vp;
    cudaGetSymbolAddress(&vp, g_cV);  float* pcV  = (float*)vp;

    const int M = Bc*Sc;  // 256

    // ---------- encoder ----------
    embed_k<<<M, 256>>>(ids, emb);
    for (int l = 0; l < Lc; l++) {
        rmsnorm_k<<<M, 256>>>(px, ph, enc_ln1 + l*Dc);
        gemm_k<<<dim3(8, 4, 3), 256>>>(ph,
            enc_wq + l*Dc*Dc, pq, enc_wk + l*Dc*Dc, pk, enc_wv + l*Dc*Dc, pv,
            nullptr, nullptr, M, Dc, Dc, nullptr, 0);
        encattn_k<<<Bc*Hc*Sc, 64>>>(mask);
        gemm_k<<<dim3(8, 4, 1), 256>>>(patt,
            enc_wo + l*Dc*Dc, px, nullptr, nullptr, nullptr, nullptr, nullptr, nullptr,
            M, Dc, Dc, px, 0);
        rmsnorm_k<<<M, 256>>>(px, ph, enc_ln2 + l*Dc);
        gemm_k<<<dim3(32, 4, 1), 256>>>(ph,
            enc_w1 + l*Dc*Fc, pff, nullptr, nullptr, nullptr, nullptr, nullptr, nullptr,
            M, Fc, Dc, nullptr, 1);
        gemm_k<<<dim3(8, 4, 1), 256>>>(pff,
            enc_w2 + l*Fc*Dc, px, nullptr, nullptr, nullptr, nullptr, nullptr, nullptr,
            M, Dc, Fc, px, 0);
    }
    rmsnorm_k<<<M, 256>>>(px, phs, enc_lnf);

    // cross-attention K/V precompute for both layers in one launch
    gemm_k<<<dim3(8, 4, 4), 256>>>(phs,
        dec_ck,           pcK,
        dec_cv,           pcV,
        dec_ck + Dc*Dc,   pcK + Bc*Sc*Dc,
        dec_cv + Dc*Dc,   pcV + Bc*Sc*Dc,
        M, Dc, Dc, nullptr, 0);

    // ---------- decoder: single megakernel for all 16 steps ----------
    int flagOK = (out_size >= Bc*Tc*Vc + Bc*Tc) ? 1 : 0;
    decode_k<<<NB, 256>>>(mask, emb,
        dec_sq, dec_sk, dec_sv, dec_so, dec_ln1,
        dec_cq, dec_co, dec_ln2,
        dec_w1, dec_w2, dec_ln3,
        dec_lnf, lm, out, flagOK);
}

// round 8
// speedup vs baseline: 1.7713x; 1.0526x over previous
#include <cuda_runtime.h>
#include <math.h>

// ---- problem constants ----
constexpr int Bc = 4;
constexpr int Sc = 64;
constexpr int Dc = 512;
constexpr int Hc = 8;
constexpr int Fc = 2048;
constexpr int Lc = 2;
constexpr int Vc = 32128;
constexpr int Tc = 16;
constexpr int NB = 148;          // megakernel blocks (all co-resident; GB300 has 152 SMs)
constexpr int NCHV = 251;        // soft-emb v-chunks (V = 251*128)
#define NEGBIG (-1e9f)

// ---- encoder scratch ----
__device__ float g_x[Bc*Sc*Dc];
__device__ float g_h[Bc*Sc*Dc];
__device__ float g_q[Bc*Sc*Dc];
__device__ float g_k[Bc*Sc*Dc];
__device__ float g_v[Bc*Sc*Dc];
__device__ float g_att[Bc*Sc*Dc];
__device__ float g_ff[Bc*Sc*Fc];
__device__ float g_hs[Bc*Sc*Dc];
__device__ float g_cK[Lc*Bc*Sc*Dc];
__device__ float g_cV[Lc*Bc*Sc*Dc];

// ---- decode scratch ----
__device__ float g_sK[Lc*Bc*Tc*Dc];
__device__ float g_sV[Lc*Bc*Tc*Dc];
__device__ float g_xd[Bc*Dc];
__device__ float g_gp1[8*4*2048];     // stage partials (KC<=8, C<=2048)
__device__ float g_gp2[16*4*512];     // head / w2 partials (<=16, C=512)
__device__ float g_logits[Bc*Vc];
__device__ float g_pmax[4*1024];
__device__ int   g_pidx[4*1024];
__device__ float g_sep[NCHV*4*512];
__device__ float g_psum[NCHV*4];

// ---- fast grid barrier: monotonic counter, red.release arrive + ld.acquire poll ----
__device__ unsigned int g_ctr = 0;
__device__ unsigned int g_done = 0;

__device__ __forceinline__ void gridbar(unsigned int& target) {
    __syncthreads();
    target += NB;
    if (threadIdx.x == 0) {
        asm volatile("red.release.gpu.global.add.u32 [%0], 1;" :: "l"(&g_ctr) : "memory");
        unsigned int v;
        do {
            asm volatile("ld.acquire.gpu.global.u32 %0, [%1];" : "=r"(v) : "l"(&g_ctr) : "memory");
        } while (v < target);
    }
    __syncthreads();
}

// =================== encoder kernels (unchanged from round 6, passing) ===================
__global__ void embed_k(const int* __restrict__ ids, const float* __restrict__ emb) {
    int bs = blockIdx.x, tid = threadIdx.x;
    int tok = ids[bs];
    for (int d = tid; d < Dc; d += 256) g_x[bs*Dc + d] = emb[tok*Dc + d];
}

__global__ void rmsnorm_k(const float* __restrict__ src, float* __restrict__ dst,
                          const float* __restrict__ w) {
    int row = blockIdx.x, tid = threadIdx.x;
    __shared__ float red[256];
    const float* s = src + row*Dc;
    float p = 0.f;
    for (int d = tid; d < Dc; d += 256) { float v = s[d]; p += v*v; }
    red[tid] = p; __syncthreads();
    for (int off = 128; off > 0; off >>= 1) {
        if (tid < off) red[tid] += red[tid + off];
        __syncthreads();
    }
    float scale = rsqrtf(red[0] / (float)Dc + 1e-6f);
    for (int d = tid; d < Dc; d += 256) dst[row*Dc + d] = s[d] * scale * w[d];
}

__global__ __launch_bounds__(256) void gemm_k(
    const float* __restrict__ A,
    const float* __restrict__ W0, float* __restrict__ C0,
    const float* __restrict__ W1, float* __restrict__ C1,
    const float* __restrict__ W2, float* __restrict__ C2,
    const float* __restrict__ W3, float* __restrict__ C3,
    int M, int N, int K,
    const float* __restrict__ resid, int relu) {
    __shared__ float As[2][16][65];
    __shared__ float Bs[2][16][65];
    int bm = blockIdx.y*64, bn = blockIdx.x*64;
    int tid = threadIdx.x;
    int tr = tid >> 4, tc = tid & 15;
    const float* W = W0; float* C = C0;
    if (blockIdx.z == 1) { W = W1; C = C1; }
    else if (blockIdx.z == 2) { W = W2; C = C2; }
    else if (blockIdx.z == 3) { W = W3; C = C3; }

    float ra[4], rb[4];
    #pragma unroll
    for (int j = 0; j < 4; j++) { int i = tid + j*256; ra[j] = A[(bm + (i>>4))*K + (i&15)]; }
    #pragma unroll
    for (int j = 0; j < 4; j++) { int i = tid + j*256; rb[j] = W[(i>>6)*N + bn + (i&63)]; }
    #pragma unroll
    for (int j = 0; j < 4; j++) { int i = tid + j*256; As[0][i&15][i>>4] = ra[j]; }
    #pragma unroll
    for (int j = 0; j < 4; j++) { int i = tid + j*256; Bs[0][i>>6][i&63] = rb[j]; }
    __syncthreads();

    float acc[4][4] = {};
    int buf = 0;
    for (int k0 = 16; k0 <= K; k0 += 16) {
        if (k0 < K) {
            #pragma unroll
            for (int j = 0; j < 4; j++) { int i = tid + j*256; ra[j] = A[(bm + (i>>4))*K + k0 + (i&15)]; }
            #pragma unroll
            for (int j = 0; j < 4; j++) { int i = tid + j*256; rb[j] = W[(k0 + (i>>6))*N + bn + (i&63)]; }
        }
        #pragma unroll
        for (int kk = 0; kk < 16; kk++) {
            float a[4], bv[4];
            #pragma unroll
            for (int i = 0; i < 4; i++) a[i] = As[buf][kk][tr*4 + i];
            #pragma unroll
            for (int j = 0; j < 4; j++) bv[j] = Bs[buf][kk][tc*4 + j];
            #pragma unroll
            for (int i = 0; i < 4; i++)
                #pragma unroll
                for (int j = 0; j < 4; j++) acc[i][j] += a[i]*bv[j];
        }
        if (k0 < K) {
            #pragma unroll
            for (int j = 0; j < 4; j++) { int i = tid + j*256; As[buf^1][i&15][i>>4] = ra[j]; }
            #pragma unroll
            for (int j = 0; j < 4; j++) { int i = tid + j*256; Bs[buf^1][i>>6][i&63] = rb[j]; }
        }
        __syncthreads();
        buf ^= 1;
    }
    #pragma unroll
    for (int i = 0; i < 4; i++)
        #pragma unroll
        for (int j = 0; j < 4; j++) {
            int r = bm + tr*4 + i, c = bn + tc*4 + j;
            float v = acc[i][j];
            if (resid) v += resid[r*N + c];
            if (relu) v = fmaxf(v, 0.f);
            C[r*N + c] = v;
        }
}

__global__ void encattn_k(const float* __restrict__ mask) {
    int blk = blockIdx.x;
    int qi = blk % Sc; int h = (blk / Sc) % Hc; int b = blk / (Sc*Hc);
    int t = threadIdx.x;  // 64
    __shared__ float qs[64], sc[64], ps[64];
    qs[t] = g_q[(b*Sc + qi)*Dc + h*64 + t];
    __syncthreads();
    const float* kr = g_k + (b*Sc + t)*Dc + h*64;
    float s = 0.f;
    #pragma unroll
    for (int d = 0; d < 64; d++) s += qs[d]*kr[d];
    s = s*0.125f + (1.0f - mask[b*Sc + t])*NEGBIG;
    sc[t] = s; __syncthreads();
    float m = -1e30f;
    for (int j = 0; j < 64; j++) m = fmaxf(m, sc[j]);
    ps[t] = expf(sc[t] - m);
    __syncthreads();
    float ssum = 0.f, o = 0.f;
    for (int j = 0; j < 64; j++) {
        ssum += ps[j];
        o += ps[j]*g_v[(b*Sc + j)*Dc + h*64 + t];
    }
    g_att[(b*Sc + qi)*Dc + h*64 + t] = o / ssum;
}

// =================== decode megakernel helpers ===================

// rms-normalize the 4x512 block in smem in place
__device__ __forceinline__ void rms_apply(float* xn, const float* __restrict__ lnw,
                                          float* red, float* rsc) {
    int rb = threadIdx.x >> 6, rt = threadIdx.x & 63;
    float p = 0.f;
    #pragma unroll
    for (int k = rt; k < 512; k += 64) { float v = xn[rb*512 + k]; p += v*v; }
    red[rb*64 + rt] = p; __syncthreads();
    #pragma unroll
    for (int off = 32; off > 0; off >>= 1) {
        if (rt < off) red[rb*64 + rt] += red[rb*64 + rt + off];
        __syncthreads();
    }
    if (threadIdx.x < 4) rsc[threadIdx.x] = rsqrtf(red[threadIdx.x*64] / 512.0f + 1e-6f);
    __syncthreads();
    for (int i = threadIdx.x; i < 2048; i += 256) xn[i] *= rsc[i >> 9] * lnw[i & 511];
    __syncthreads();
}

// fold npend gp2 partials into s_xd (redundant per block)
__device__ __forceinline__ void fold_gp2(float* s_xd, int npend) {
    for (int i = threadIdx.x; i < 2048; i += 256) {
        int b = i >> 9, k = i & 511;
        float s = s_xd[i];
        for (int j = 0; j < npend; j++) s += g_gp2[(j*4 + b)*512 + k];
        s_xd[i] = s;
    }
    __syncthreads();
}

// generic partial GEMV: (C/32 tiles) x KC chunks warp tasks -> gp1
__device__ __forceinline__ void gemv_part(const float* __restrict__ W, const float* xn,
                                          int C, int KC, int ck) {
    int warp = threadIdx.x >> 5, lane = threadIdx.x & 31;
    int ntiles = C >> 5;
    int ntasks = ntiles * KC;
    for (int tt = blockIdx.x + warp*NB; tt < ntasks; tt += NB*8) {
        int tile = tt % ntiles, kc = tt / ntiles;
        int n = (tile << 5) + lane;
        int k0 = kc*ck, k1 = k0 + ck;
        float a0 = 0.f, a1 = 0.f, a2 = 0.f, a3 = 0.f;
        #pragma unroll 8
        for (int k = k0; k < k1; k++) {
            float w = W[k*C + n];
            a0 += xn[k]*w; a1 += xn[512+k]*w; a2 += xn[1024+k]*w; a3 += xn[1536+k]*w;
        }
        g_gp1[(kc*4+0)*2048 + n] = a0;
        g_gp1[(kc*4+1)*2048 + n] = a1;
        g_gp1[(kc*4+2)*2048 + n] = a2;
        g_gp1[(kc*4+3)*2048 + n] = a3;
    }
}

// fused q/k/v partials (virtual C=1536), KC=8 -> gp1
__device__ __forceinline__ void qkv_part(const float* __restrict__ Wq,
                                         const float* __restrict__ Wk,
                                         const float* __restrict__ Wv,
                                         const float* xn) {
    int warp = threadIdx.x >> 5, lane = threadIdx.x & 31;
    for (int tt = blockIdx.x + warp*NB; tt < 48*8; tt += NB*8) {
        int tile = tt % 48, kc = tt / 48;
        const float* W = (tile < 16) ? Wq : (tile < 32 ? Wk : Wv);
        int nloc = ((tile & 15) << 5) + lane;
        int k0 = kc*64;
        float a0 = 0.f, a1 = 0.f, a2 = 0.f, a3 = 0.f;
        #pragma unroll 8
        for (int k = k0; k < k0+64; k++) {
            float w = W[k*512 + nloc];
            a0 += xn[k]*w; a1 += xn[512+k]*w; a2 += xn[1024+k]*w; a3 += xn[1536+k]*w;
        }
        int n = tile*32 + lane;
        g_gp1[(kc*4+0)*2048 + n] = a0;
        g_gp1[(kc*4+1)*2048 + n] = a1;
        g_gp1[(kc*4+2)*2048 + n] = a2;
        g_gp1[(kc*4+3)*2048 + n] = a3;
    }
}

// =================== the decode megakernel ===================
__global__ __launch_bounds__(256) void decode_k(
    const float* __restrict__ mask, const float* __restrict__ emb,
    const float* __restrict__ sqw, const float* __restrict__ skw, const float* __restrict__ svw,
    const float* __restrict__ sow, const float* __restrict__ ln1,
    const float* __restrict__ cqw, const float* __restrict__ cow, const float* __restrict__ ln2,
    const float* __restrict__ w1w, const float* __restrict__ w2w, const float* __restrict__ ln3,
    const float* __restrict__ lnf, const float* __restrict__ lm,
    float* __restrict__ out, int flagOK)
{
    __shared__ float s_xd[2048];
    __shared__ float s_xn[2048];
    __shared__ float s_ws[8*512];
    __shared__ float s_red[256];
    __shared__ int   s_idx[256];
    __shared__ float s_rsc[4];
    __shared__ float s_q[64], s_sc[64], s_ps[64], s_ao[64];
    __shared__ float s_ev[4*128];
    __shared__ float s_gmax[4];
    int tid = threadIdx.x;
    int bid = blockIdx.x;
    unsigned int bar = 0;

    for (int p = 0; p < Tc; p++) {
        // load xd (step 0: pad embedding; else FIN output)
        if (p == 0) {
            for (int i = tid; i < 2048; i += 256) s_xd[i] = emb[i & 511];
        } else {
            for (int i = tid; i < 2048; i += 256) s_xd[i] = g_xd[i];
        }
        __syncthreads();

        for (int l = 0; l < Lc; l++) {
            if (l > 0) fold_gp2(s_xd, 16);   // fold previous layer's w2 partials
            // --- S1: rms(ln1) -> xn; qkv partials
            for (int i = tid; i < 2048; i += 256) s_xn[i] = s_xd[i];
            __syncthreads();
            rms_apply(s_xn, ln1 + l*512, s_red, s_rsc);
            qkv_part(sqw + l*512*512, skw + l*512*512, svw + l*512*512, s_xn);
            gridbar(bar);

            // --- S2: per-(b,h) self-attention + fused o-projection (32 blocks)
            if (bid < 32) {
                int b = bid >> 3, h = bid & 7;
                int nk = p + 1;
                if (tid < 64) {
                    int col = h*64 + tid;
                    float qv = 0.f, kn = 0.f, vn = 0.f;
                    #pragma unroll
                    for (int kc = 0; kc < 8; kc++) {
                        const float* gp = g_gp1 + (kc*4+b)*2048;
                        qv += gp[col]; kn += gp[512 + col]; vn += gp[1024 + col];
                    }
                    s_q[tid] = qv;
                    g_sK[((l*Bc + b)*Tc + p)*512 + col] = kn;
                    g_sV[((l*Bc + b)*Tc + p)*512 + col] = vn;
                }
                __syncthreads();
                if (tid < 64 && tid < nk) {
                    const float* kr = g_sK + ((l*Bc + b)*Tc + tid)*512 + h*64;
                    float s = 0.f;
                    #pragma unroll
                    for (int d = 0; d < 64; d++) s += s_q[d]*kr[d];
                    s_sc[tid] = s*0.125f;
                }
                __syncthreads();
                if (tid < 64) {
                    float m = -1e30f;
                    for (int j = 0; j < nk; j++) m = fmaxf(m, s_sc[j]);
                    float ssum = 0.f, o = 0.f;
                    for (int j = 0; j < nk; j++) {
                        float e = expf(s_sc[j] - m);
                        ssum += e;
                        o += e*g_sV[((l*Bc + b)*Tc + j)*512 + h*64 + tid];
                    }
                    s_ao[tid] = o/ssum;
                }
                __syncthreads();
                // fused o-projection for this head: ao[64] @ Wo[h*64:(h+1)*64, :]
                {
                    const float* Wb = sow + l*512*512 + h*64*512;
                    float acc0 = 0.f, acc1 = 0.f;
                    #pragma unroll 8
                    for (int d = 0; d < 64; d++) {
                        float a = s_ao[d];
                        acc0 += a*Wb[d*512 + tid];
                        acc1 += a*Wb[d*512 + tid + 256];
                    }
                    g_gp2[(h*4+b)*512 + tid] = acc0;
                    g_gp2[(h*4+b)*512 + tid + 256] = acc1;
                }
            }
            gridbar(bar);

            // --- S3: fold heads + rms(ln2) -> xn; cq partials
            fold_gp2(s_xd, 8);
            for (int i = tid; i < 2048; i += 256) s_xn[i] = s_xd[i];
            __syncthreads();
            rms_apply(s_xn, ln2 + l*512, s_red, s_rsc);
            gemv_part(cqw + l*512*512, s_xn, 512, 8, 64);
            gridbar(bar);

            // --- S4: per-(b,h) cross-attention + fused co-projection (32 blocks)
            if (bid < 32) {
                int b = bid >> 3, h = bid & 7;
                if (tid < 64) {
                    float qv = 0.f;
                    #pragma unroll
                    for (int kc = 0; kc < 8; kc++) qv += g_gp1[(kc*4+b)*2048 + h*64 + tid];
                    s_q[tid] = qv;
                }
                __syncthreads();
                if (tid < 64) {
                    const float* kr = g_cK + ((l*Bc + b)*Sc + tid)*512 + h*64;
                    float s = 0.f;
                    #pragma unroll
                    for (int d = 0; d < 64; d++) s += s_q[d]*kr[d];
                    s_sc[tid] = s*0.125f + (1.0f - mask[b*Sc + tid])*NEGBIG;
                }
                __syncthreads();
                if (tid < 64) {
                    float m = -1e30f;
                    for (int j = 0; j < 64; j++) m = fmaxf(m, s_sc[j]);
                    s_ps[tid] = expf(s_sc[tid] - m);
                }
                __syncthreads();
                if (tid < 64) {
                    float ssum = 0.f, o = 0.f;
                    #pragma unroll 8
                    for (int j = 0; j < 64; j++) {
                        ssum += s_ps[j];
                        o += s_ps[j]*g_cV[((l*Bc + b)*Sc + j)*512 + h*64 + tid];
                    }
                    s_ao[tid] = o/ssum;
                }
                __syncthreads();
                {
                    const float* Wb = cow + l*512*512 + h*64*512;
                    float acc0 = 0.f, acc1 = 0.f;
                    #pragma unroll 8
                    for (int d = 0; d < 64; d++) {
                        float a = s_ao[d];
                        acc0 += a*Wb[d*512 + tid];
                        acc1 += a*Wb[d*512 + tid + 256];
                    }
                    g_gp2[(h*4+b)*512 + tid] = acc0;
                    g_gp2[(h*4+b)*512 + tid + 256] = acc1;
                }
            }
            gridbar(bar);

            // --- S5: fold heads + rms(ln3) -> xn; w1 partials (C=2048)
            fold_gp2(s_xd, 8);
            for (int i = tid; i < 2048; i += 256) s_xn[i] = s_xd[i];
            __syncthreads();
            rms_apply(s_xn, ln3 + l*512, s_red, s_rsc);
            gemv_part(w1w + l*512*2048, s_xn, 2048, 8, 64);
            gridbar(bar);

            // --- S6: w2 warp tasks: slice-combine+relu then partial GEMV (KC=16, ck=128)
            {
                int warp = tid >> 5, lane = tid & 31;
                float* fs = s_ws + warp*512;
                for (int tt = bid + warp*NB; tt < 16*16; tt += NB*8) {
                    int tile = tt & 15, kc = tt >> 4;
                    int n = (tile << 5) + lane;
                    int k0 = kc*128;
                    // combine+relu the needed f slice: f[b][k0..k0+127]
                    for (int idx = lane; idx < 512; idx += 32) {
                        int b = idx >> 7, kk = idx & 127;
                        float s = 0.f;
                        #pragma unroll
                        for (int j = 0; j < 8; j++) s += g_gp1[(j*4+b)*2048 + k0 + kk];
                        fs[idx] = fmaxf(s, 0.f);
                    }
                    __syncwarp();
                    float a0 = 0.f, a1 = 0.f, a2 = 0.f, a3 = 0.f;
                    const float* Wb = w2w + l*2048*512;
                    #pragma unroll 8
                    for (int kk = 0; kk < 128; kk++) {
                        float w = Wb[(k0 + kk)*512 + n];
                        a0 += fs[kk]*w; a1 += fs[128+kk]*w;
                        a2 += fs[256+kk]*w; a3 += fs[384+kk]*w;
                    }
                    g_gp2[(kc*4+0)*512 + n] = a0;
                    g_gp2[(kc*4+1)*512 + n] = a1;
                    g_gp2[(kc*4+2)*512 + n] = a2;
                    g_gp2[(kc*4+3)*512 + n] = a3;
                    __syncwarp();
                }
            }
            gridbar(bar);
        }

        // --- LM: fold w2 + rms(lnf) -> xn; lm head partials
        fold_gp2(s_xd, 16);
        for (int i = tid; i < 2048; i += 256) s_xn[i] = s_xd[i];
        __syncthreads();
        rms_apply(s_xn, lnf, s_red, s_rsc);
        {
            int warp = tid >> 5, lane = tid & 31;
            const unsigned full = 0xffffffffu;
            for (int tt = bid + warp*NB; tt < 1004; tt += NB*8) {
                int n = tt*32 + lane;
                float a0 = 0.f, a1 = 0.f, a2 = 0.f, a3 = 0.f;
                #pragma unroll 16
                for (int k = 0; k < 512; k++) {
                    float w = lm[k*Vc + n];
                    a0 += s_xn[k]*w; a1 += s_xn[512+k]*w;
                    a2 += s_xn[1024+k]*w; a3 += s_xn[1536+k]*w;
                }
                g_logits[0*Vc + n] = a0; g_logits[1*Vc + n] = a1;
                g_logits[2*Vc + n] = a2; g_logits[3*Vc + n] = a3;
                float vals[4] = {a0, a1, a2, a3};
                #pragma unroll
                for (int b = 0; b < 4; b++) {
                    float mv = vals[b]; int mi = n;
                    #pragma unroll
                    for (int off = 16; off > 0; off >>= 1) {
                        float v2 = __shfl_down_sync(full, mv, off);
                        int   i2 = __shfl_down_sync(full, mi, off);
                        if (v2 > mv || (v2 == mv && i2 < mi)) { mv = v2; mi = i2; }
                    }
                    if (lane == 0) { g_pmax[b*1024 + tt] = mv; g_pidx[b*1024 + tt] = mi; }
                }
            }
        }
        gridbar(bar);

        // --- SE: softmax + soft-embedding chunk partials
        {
            #pragma unroll
            for (int b = 0; b < 4; b++) {
                float m = -1e30f;
                for (int t2 = tid; t2 < 1004; t2 += 256) m = fmaxf(m, g_pmax[b*1024 + t2]);
                s_red[tid] = m; __syncthreads();
                #pragma unroll
                for (int off = 128; off > 0; off >>= 1) {
                    if (tid < off) s_red[tid] = fmaxf(s_red[tid], s_red[tid + off]);
                    __syncthreads();
                }
                if (tid == 0) s_gmax[b] = s_red[0];
                __syncthreads();
            }
            for (int ch = bid; ch < NCHV; ch += NB) {
                int v0 = ch*128;
                if (tid < 128) {
                    int v = v0 + tid;
                    #pragma unroll
                    for (int b = 0; b < 4; b++) {
                        float e = expf(g_logits[b*Vc + v] - s_gmax[b]);
                        s_ev[b*128 + tid] = e;
                        out[((size_t)b*Tc + p)*Vc + v] = e;   // unnormalized; FIN scales
                    }
                }
                __syncthreads();
                int d0 = tid, d1 = tid + 256;
                float a00=0,a01=0,a02=0,a03=0,a10=0,a11=0,a12=0,a13=0;
                #pragma unroll 4
                for (int v = 0; v < 128; v++) {
                    float w0 = emb[(size_t)(v0+v)*512 + d0];
                    float w1 = emb[(size_t)(v0+v)*512 + d1];
                    float e0 = s_ev[v], e1 = s_ev[128+v], e2 = s_ev[256+v], e3 = s_ev[384+v];
                    a00 += e0*w0; a01 += e1*w0; a02 += e2*w0; a03 += e3*w0;
                    a10 += e0*w1; a11 += e1*w1; a12 += e2*w1; a13 += e3*w1;
                }
                g_sep[(ch*4+0)*512 + d0] = a00; g_sep[(ch*4+1)*512 + d0] = a01;
                g_sep[(ch*4+2)*512 + d0] = a02; g_sep[(ch*4+3)*512 + d0] = a03;
                g_sep[(ch*4+0)*512 + d1] = a10; g_sep[(ch*4+1)*512 + d1] = a11;
                g_sep[(ch*4+2)*512 + d1] = a12; g_sep[(ch*4+3)*512 + d1] = a13;
                if (tid < 4) {
                    float s = 0.f;
                    for (int v = 0; v < 128; v++) s += s_ev[tid*128 + v];
                    g_psum[ch*4 + tid] = s;
                }
                __syncthreads();
            }
        }
        gridbar(bar);

        // --- FIN: normalize probs, next xd, pad flag
        {
            #pragma unroll
            for (int b = 0; b < 4; b++) {
                float s = 0.f;
                for (int c = tid; c < NCHV; c += 256) s += g_psum[c*4 + b];
                s_red[tid] = s; __syncthreads();
                #pragma unroll
                for (int off = 128; off > 0; off >>= 1) {
                    if (tid < off) s_red[tid] += s_red[tid + off];
                    __syncthreads();
                }
                if (tid == 0) s_rsc[b] = 1.0f / s_red[0];
                __syncthreads();
            }
            size_t gt = (size_t)bid*256 + tid;
            for (size_t i = gt; i < (size_t)4*Vc; i += (size_t)NB*256) {
                int b = (int)(i / Vc); int v = (int)(i % Vc);
                out[((size_t)b*Tc + p)*Vc + v] *= s_rsc[b];
            }
            for (int i = (int)gt; i < 2048; i += NB*256) {
                int b = i >> 9, k = i & 511;
                float s = 0.f;
                #pragma unroll 8
                for (int c = 0; c < NCHV; c++) s += g_sep[(c*4+b)*512 + k];
                g_xd[i] = s * s_rsc[b];
            }
            if (bid == 0 && flagOK) {
                for (int b = 0; b < 4; b++) {
                    float mv = -1e30f; int mi = 0x7fffffff;
                    for (int t2 = tid; t2 < 1004; t2 += 256) {
                        float v = g_pmax[b*1024 + t2]; int i2 = g_pidx[b*1024 + t2];
                        if (v > mv || (v == mv && i2 < mi)) { mv = v; mi = i2; }
                    }
                    s_red[tid] = mv; s_idx[tid] = mi; __syncthreads();
                    #pragma unroll
                    for (int off = 128; off > 0; off >>= 1) {
                        if (tid < off) {
                            float v2 = s_red[tid + off]; int i2 = s_idx[tid + off];
                            if (v2 > s_red[tid] || (v2 == s_red[tid] && i2 < s_idx[tid])) {
                                s_red[tid] = v2; s_idx[tid] = i2;
                            }
                        }
                        __syncthreads();
                    }
                    if (tid == 0)
                        out[(size_t)Bc*Tc*Vc + b*Tc + p] = (s_idx[0] == 0) ? 1.0f : 0.0f;
                    __syncthreads();
                }
            }
        }
        gridbar(bar);
    }

    // end-of-kernel handshake: reset counters so graph replays start clean
    __syncthreads();
    if (tid == 0)
        asm volatile("red.release.gpu.global.add.u32 [%0], 1;" :: "l"(&g_done) : "memory");
    if (bid == 0 && tid == 0) {
        unsigned int v;
        do {
            asm volatile("ld.acquire.gpu.global.u32 %0, [%1];" : "=r"(v) : "l"(&g_done) : "memory");
        } while (v < NB);
        g_ctr = 0;
        g_done = 0;
    }
}

// ======================= host =======================
extern "C" void kernel_launch(void* const* d_in, const int* in_sizes, int n_in,
                              void* d_out, int out_size) {
    const int*   ids     = (const int*)d_in[0];
    const float* mask    = (const float*)d_in[1];
    const float* emb     = (const float*)d_in[2];
    const float* enc_wq  = (const float*)d_in[3];
    const float* enc_wk  = (const float*)d_in[4];
    const float* enc_wv  = (const float*)d_in[5];
    const float* enc_wo  = (const float*)d_in[6];
    const float* enc_ln1 = (const float*)d_in[7];
    const float* enc_w1  = (const float*)d_in[8];
    const float* enc_w2  = (const float*)d_in[9];
    const float* enc_ln2 = (const float*)d_in[10];
    const float* enc_lnf = (const float*)d_in[11];
    const float* dec_sq  = (const float*)d_in[12];
    const float* dec_sk  = (const float*)d_in[13];
    const float* dec_sv  = (const float*)d_in[14];
    const float* dec_so  = (const float*)d_in[15];
    const float* dec_ln1 = (const float*)d_in[16];
    const float* dec_cq  = (const float*)d_in[17];
    const float* dec_ck  = (const float*)d_in[18];
    const float* dec_cv  = (const float*)d_in[19];
    const float* dec_co  = (const float*)d_in[20];
    const float* dec_ln2 = (const float*)d_in[21];
    const float* dec_w1  = (const float*)d_in[22];
    const float* dec_w2  = (const float*)d_in[23];
    const float* dec_ln3 = (const float*)d_in[24];
    const float* dec_lnf = (const float*)d_in[25];
    const float* lm      = (const float*)d_in[26];
    float* out = (float*)d_out;

    void* vp;
    cudaGetSymbolAddress(&vp, g_x);   float* px   = (float*)vp;
    cudaGetSymbolAddress(&vp, g_h);   float* ph   = (float*)vp;
    cudaGetSymbolAddress(&vp, g_q);   float* pq   = (float*)vp;
    cudaGetSymbolAddress(&vp, g_k);   float* pk   = (float*)vp;
    cudaGetSymbolAddress(&vp, g_v);   float* pv   = (float*)vp;
    cudaGetSymbolAddress(&vp, g_att); float* patt = (float*)vp;
    cudaGetSymbolAddress(&vp, g_ff);  float* pff  = (float*)vp;
    cudaGetSymbolAddress(&vp, g_hs);  float* phs  = (float*)vp;
    cudaGetSymbolAddress(&vp, g_cK);  float* pcK  = (float*)vp;
    cudaGetSymbolAddress(&vp, g_cV);  float* pcV  = (float*)vp;

    const int M = Bc*Sc;  // 256

    // ---------- encoder ----------
    embed_k<<<M, 256>>>(ids, emb);
    for (int l = 0; l < Lc; l++) {
        rmsnorm_k<<<M, 256>>>(px, ph, enc_ln1 + l*Dc);
        gemm_k<<<dim3(8, 4, 3), 256>>>(ph,
            enc_wq + l*Dc*Dc, pq, enc_wk + l*Dc*Dc, pk, enc_wv + l*Dc*Dc, pv,
            nullptr, nullptr, M, Dc, Dc, nullptr, 0);
        encattn_k<<<Bc*Hc*Sc, 64>>>(mask);
        gemm_k<<<dim3(8, 4, 1), 256>>>(patt,
            enc_wo + l*Dc*Dc, px, nullptr, nullptr, nullptr, nullptr, nullptr, nullptr,
            M, Dc, Dc, px, 0);
        rmsnorm_k<<<M, 256>>>(px, ph, enc_ln2 + l*Dc);
        gemm_k<<<dim3(32, 4, 1), 256>>>(ph,
            enc_w1 + l*Dc*Fc, pff, nullptr, nullptr, nullptr, nullptr, nullptr, nullptr,
            M, Fc, Dc, nullptr, 1);
        gemm_k<<<dim3(8, 4, 1), 256>>>(pff,
            enc_w2 + l*Fc*Dc, px, nullptr, nullptr, nullptr, nullptr, nullptr, nullptr,
            M, Dc, Fc, px, 0);
    }
    rmsnorm_k<<<M, 256>>>(px, phs, enc_lnf);

    // cross-attention K/V precompute for both layers in one launch
    gemm_k<<<dim3(8, 4, 4), 256>>>(phs,
        dec_ck,           pcK,
        dec_cv,           pcV,
        dec_ck + Dc*Dc,   pcK + Bc*Sc*Dc,
        dec_cv + Dc*Dc,   pcV + Bc*Sc*Dc,
        M, Dc, Dc, nullptr, 0);

    // ---------- decoder: single megakernel for all 16 steps ----------
    int flagOK = (out_size >= Bc*Tc*Vc + Bc*Tc) ? 1 : 0;
    decode_k<<<NB, 256>>>(mask, emb,
        dec_sq, dec_sk, dec_sv, dec_so, dec_ln1,
        dec_cq, dec_co, dec_ln2,
        dec_w1, dec_w2, dec_ln3,
        dec_lnf, lm, out, flagOK);
}

// round 11
// speedup vs baseline: 4.0453x; 2.2839x over previous
#include <cuda_runtime.h>
#include <math.h>

// ---- problem constants ----
constexpr int Bc = 4;
constexpr int Sc = 64;
constexpr int Dc = 512;
constexpr int Hc = 8;
constexpr int Fc = 2048;
constexpr int Lc = 2;
constexpr int Vc = 32128;
constexpr int V4 = Vc/4;       // 8032
constexpr int Tc = 16;
constexpr int NB = 148;
#define NEGBIG (-1e9f)

// ---- encoder scratch ----
__device__ __align__(16) float g_x[Bc*Sc*Dc];
__device__ __align__(16) float g_h[Bc*Sc*Dc];
__device__ __align__(16) float g_q[Bc*Sc*Dc];
__device__ __align__(16) float g_k[Bc*Sc*Dc];
__device__ __align__(16) float g_v[Bc*Sc*Dc];
__device__ __align__(16) float g_att[Bc*Sc*Dc];
__device__ __align__(16) float g_ff[Bc*Sc*Fc];
__device__ __align__(16) float g_hs[Bc*Sc*Dc];
__device__ __align__(16) float g_cK[Lc*Bc*Sc*Dc];
__device__ __align__(16) float g_cV[Lc*Bc*Sc*Dc];

// ---- decode scratch ----
__device__ __align__(16) float g_sK[Lc*Bc*Tc*Dc];
__device__ __align__(16) float g_sV[Lc*Bc*Tc*Dc];
__device__ __align__(16) float g_xd[Bc*Dc];
__device__ __align__(16) float g_gp1[8*4*2048];     // layer-stage partials
__device__ __align__(16) float g_gp2[16*4*512];     // head / w2 partials
__device__ __align__(16) float g_lmp[8*4*Vc];       // lm-head partials (4.1MB)
__device__ __align__(16) float g_logits[Bc*Vc];
__device__ __align__(16) float g_sepB[NB*4*512];    // per-block soft-emb partials
__device__ float g_psumB[NB*4];
__device__ float g_bmax[4*NB];
__device__ int   g_bmaxi[4*NB];

// ---- grid barrier: monotonic counter ----
__device__ unsigned int g_ctr = 0;
__device__ unsigned int g_done = 0;

__device__ __forceinline__ void gridbar(unsigned int& target) {
    __syncthreads();
    target += NB;
    if (threadIdx.x == 0) {
        asm volatile("red.release.gpu.global.add.u32 [%0], 1;" :: "l"(&g_ctr) : "memory");
        unsigned int v;
        do {
            asm volatile("ld.acquire.gpu.global.u32 %0, [%1];" : "=r"(v) : "l"(&g_ctr) : "memory");
        } while (v < target);
    }
    __syncthreads();
}

// =================== encoder kernels ===================
__global__ void embed_k(const int* __restrict__ ids, const float* __restrict__ emb) {
    int bs = blockIdx.x, tid = threadIdx.x;
    int tok = ids[bs];
    for (int d = tid; d < Dc; d += 256) g_x[bs*Dc + d] = emb[tok*Dc + d];
}

__global__ void rmsnorm_k(const float* __restrict__ src, float* __restrict__ dst,
                          const float* __restrict__ w) {
    int row = blockIdx.x, tid = threadIdx.x;
    __shared__ float red[256];
    const float* s = src + row*Dc;
    float p = 0.f;
    for (int d = tid; d < Dc; d += 256) { float v = s[d]; p += v*v; }
    red[tid] = p; __syncthreads();
    for (int off = 128; off > 0; off >>= 1) {
        if (tid < off) red[tid] += red[tid + off];
        __syncthreads();
    }
    float scale = rsqrtf(red[0] / (float)Dc + 1e-6f);
    for (int d = tid; d < Dc; d += 256) dst[row*Dc + d] = s[d] * scale * w[d];
}

__global__ __launch_bounds__(256) void gemm_k(
    const float* __restrict__ A,
    const float* __restrict__ W0, float* __restrict__ C0,
    const float* __restrict__ W1, float* __restrict__ C1,
    const float* __restrict__ W2, float* __restrict__ C2,
    const float* __restrict__ W3, float* __restrict__ C3,
    int M, int N, int K,
    const float* __restrict__ resid, int relu) {
    __shared__ float As[2][16][65];
    __shared__ float Bs[2][16][65];
    int bm = blockIdx.y*64, bn = blockIdx.x*64;
    int tid = threadIdx.x;
    int tr = tid >> 4, tc = tid & 15;
    const float* W = W0; float* C = C0;
    if (blockIdx.z == 1) { W = W1; C = C1; }
    else if (blockIdx.z == 2) { W = W2; C = C2; }
    else if (blockIdx.z == 3) { W = W3; C = C3; }

    int ar = tid >> 2, ac = (tid & 3)*4;      // A: 64 rows x 16 cols, one float4/thread
    int br = tid >> 4, bcc = (tid & 15)*4;    // B: 16 rows x 64 cols, one float4/thread

    float4 ra4 = *(const float4*)&A[(bm + ar)*K + ac];
    float4 rb4 = *(const float4*)&W[br*N + bn + bcc];
    As[0][ac+0][ar] = ra4.x; As[0][ac+1][ar] = ra4.y; As[0][ac+2][ar] = ra4.z; As[0][ac+3][ar] = ra4.w;
    Bs[0][br][bcc+0] = rb4.x; Bs[0][br][bcc+1] = rb4.y; Bs[0][br][bcc+2] = rb4.z; Bs[0][br][bcc+3] = rb4.w;
    __syncthreads();

    float acc[4][4] = {};
    int buf = 0;
    for (int k0 = 16; k0 <= K; k0 += 16) {
        if (k0 < K) {
            ra4 = *(const float4*)&A[(bm + ar)*K + k0 + ac];
            rb4 = *(const float4*)&W[(k0 + br)*N + bn + bcc];
        }
        #pragma unroll
        for (int kk = 0; kk < 16; kk++) {
            float a[4], bv[4];
            #pragma unroll
            for (int i = 0; i < 4; i++) a[i] = As[buf][kk][tr*4 + i];
            #pragma unroll
            for (int j = 0; j < 4; j++) bv[j] = Bs[buf][kk][tc*4 + j];
            #pragma unroll
            for (int i = 0; i < 4; i++)
                #pragma unroll
                for (int j = 0; j < 4; j++) acc[i][j] += a[i]*bv[j];
        }
        if (k0 < K) {
            As[buf^1][ac+0][ar] = ra4.x; As[buf^1][ac+1][ar] = ra4.y;
            As[buf^1][ac+2][ar] = ra4.z; As[buf^1][ac+3][ar] = ra4.w;
            Bs[buf^1][br][bcc+0] = rb4.x; Bs[buf^1][br][bcc+1] = rb4.y;
            Bs[buf^1][br][bcc+2] = rb4.z; Bs[buf^1][br][bcc+3] = rb4.w;
        }
        __syncthreads();
        buf ^= 1;
    }
    #pragma unroll
    for (int i = 0; i < 4; i++)
        #pragma unroll
        for (int j = 0; j < 4; j++) {
            int r = bm + tr*4 + i, c = bn + tc*4 + j;
            float v = acc[i][j];
            if (resid) v += resid[r*N + c];
            if (relu) v = fmaxf(v, 0.f);
            C[r*N + c] = v;
        }
}

__global__ void encattn_k(const float* __restrict__ mask) {
    int blk = blockIdx.x;
    int qi = blk % Sc; int h = (blk / Sc) % Hc; int b = blk / (Sc*Hc);
    int t = threadIdx.x;  // 64
    __shared__ float qs[64], sc[64], ps[64];
    qs[t] = g_q[(b*Sc + qi)*Dc + h*64 + t];
    __syncthreads();
    const float4* kr4 = (const float4*)&g_k[(b*Sc + t)*Dc + h*64];
    float s = 0.f;
    #pragma unroll
    for (int d4 = 0; d4 < 16; d4++) {
        float4 k4 = kr4[d4];
        s += qs[d4*4]*k4.x + qs[d4*4+1]*k4.y + qs[d4*4+2]*k4.z + qs[d4*4+3]*k4.w;
    }
    s = s*0.125f + (1.0f - mask[b*Sc + t])*NEGBIG;
    sc[t] = s; __syncthreads();
    float m = -1e30f;
    for (int j = 0; j < 64; j++) m = fmaxf(m, sc[j]);
    ps[t] = expf(sc[t] - m);
    __syncthreads();
    float ssum = 0.f, o = 0.f;
    #pragma unroll 8
    for (int j = 0; j < 64; j++) {
        ssum += ps[j];
        o += ps[j]*g_v[(b*Sc + j)*Dc + h*64 + t];
    }
    g_att[(b*Sc + qi)*Dc + h*64 + t] = o / ssum;
}

// =================== decode megakernel ===================
__global__ __launch_bounds__(512) void decode_k(
    const float* __restrict__ mask, const float* __restrict__ emb,
    const float* __restrict__ sqw, const float* __restrict__ skw, const float* __restrict__ svw,
    const float* __restrict__ sow, const float* __restrict__ ln1,
    const float* __restrict__ cqw, const float* __restrict__ cow, const float* __restrict__ ln2,
    const float* __restrict__ w1w, const float* __restrict__ w2w, const float* __restrict__ ln3,
    const float* __restrict__ lnf, const float* __restrict__ lm,
    float* __restrict__ out, int flagOK)
{
    extern __shared__ float4 dyn4[];
    float4* s_xd4 = dyn4;              // 512 f4  (8KB)
    float4* s_xn4 = dyn4 + 512;        // 512 f4  (8KB)
    float4* s_ws4 = dyn4 + 1024;       // 2048 f4 (32KB)
    float*  s_xn  = (float*)s_xn4;
    float*  s_ws  = (float*)s_ws4;
    __shared__ float s_red[512];
    __shared__ int   s_idx[512];
    __shared__ float s_rsc[8];
    __shared__ float s_q[64], s_sc[64], s_ao[64], s_ps[64];
    __shared__ float s_ev[512];
    __shared__ float s_gmax[4];

    int tid = threadIdx.x, bid = blockIdx.x;
    int warp = tid >> 5, lane = tid & 31;
    unsigned int bar = 0;

    float4* g_gp14  = (float4*)g_gp1;
    float4* g_gp24  = (float4*)g_gp2;
    float4* g_lmp4  = (float4*)g_lmp;
    float4* g_log4  = (float4*)g_logits;
    float4* g_sepB4 = (float4*)g_sepB;
    float4* g_xd4   = (float4*)g_xd;
    const float4* emb4 = (const float4*)emb;
    const float4* lm4  = (const float4*)lm;
    float4* out4 = (float4*)out;

    // rms helper (inline lambda-style via macro-free code duplication below)
    auto rms512 = [&](const float* lnw) {
        int rb = tid >> 7, rt = tid & 127;
        float pp = 0.f;
        #pragma unroll
        for (int k = rt; k < 512; k += 128) { float v = s_xn[rb*512 + k]; pp += v*v; }
        s_red[rb*128 + rt] = pp; __syncthreads();
        #pragma unroll
        for (int off = 64; off > 0; off >>= 1) {
            if (rt < off) s_red[rb*128 + rt] += s_red[rb*128 + rt + off];
            __syncthreads();
        }
        if (tid < 4) s_rsc[tid] = rsqrtf(s_red[tid*128] / 512.0f + 1e-6f);
        __syncthreads();
        for (int i = tid; i < 2048; i += 512) s_xn[i] *= s_rsc[i >> 9] * lnw[i & 511];
        __syncthreads();
    };
    auto fold_gp2 = [&](int cnt) {   // s_xd4[tid] += sum of cnt partials
        int b = tid >> 7, n4 = tid & 127;
        float4 s = s_xd4[tid];
        for (int j = 0; j < cnt; j++) {
            float4 t4 = g_gp24[(j*4 + b)*128 + n4];
            s.x += t4.x; s.y += t4.y; s.z += t4.z; s.w += t4.w;
        }
        s_xd4[tid] = s;
        __syncthreads();
    };

    for (int p = 0; p < Tc; p++) {
        // load xd
        if (p == 0) s_xd4[tid] = emb4[tid & 127];
        else        s_xd4[tid] = g_xd4[tid];
        __syncthreads();

        for (int l = 0; l < Lc; l++) {
            if (l > 0) fold_gp2(16);
            // --- S1: rms(ln1); qkv partials (96 tasks)
            s_xn4[tid] = s_xd4[tid]; __syncthreads();
            rms512(ln1 + l*512);
            {
                int tt = bid + warp*NB;
                if (tt < 96) {
                    int tile = tt % 12, kc = tt / 12;
                    const float* W = (tile < 4) ? (sqw + l*262144)
                                   : (tile < 8) ? (skw + l*262144) : (svw + l*262144);
                    int nloc = (tile & 3)*128 + lane*4;
                    int k0 = kc*64;
                    float4 a0 = {0,0,0,0}, a1 = {0,0,0,0}, a2 = {0,0,0,0}, a3 = {0,0,0,0};
                    #pragma unroll 16
                    for (int k = k0; k < k0 + 64; k++) {
                        float4 w4 = *(const float4*)&W[k*512 + nloc];
                        float x0 = s_xn[k], x1 = s_xn[512+k], x2 = s_xn[1024+k], x3 = s_xn[1536+k];
                        a0.x += x0*w4.x; a0.y += x0*w4.y; a0.z += x0*w4.z; a0.w += x0*w4.w;
                        a1.x += x1*w4.x; a1.y += x1*w4.y; a1.z += x1*w4.z; a1.w += x1*w4.w;
                        a2.x += x2*w4.x; a2.y += x2*w4.y; a2.z += x2*w4.z; a2.w += x2*w4.w;
                        a3.x += x3*w4.x; a3.y += x3*w4.y; a3.z += x3*w4.z; a3.w += x3*w4.w;
                    }
                    int n4 = (tile*128 + lane*4) >> 2;
                    g_gp14[(kc*4+0)*512 + n4] = a0;
                    g_gp14[(kc*4+1)*512 + n4] = a1;
                    g_gp14[(kc*4+2)*512 + n4] = a2;
                    g_gp14[(kc*4+3)*512 + n4] = a3;
                }
            }
            gridbar(bar);

            // --- S2: self attention + o-proj (32 blocks)
            if (bid < 32) {
                int b = bid >> 3, h = bid & 7;
                int nk = p + 1;
                if (tid < 64) {
                    int col = h*64 + tid;
                    float qv = 0.f, kn = 0.f, vn = 0.f;
                    #pragma unroll
                    for (int kc = 0; kc < 8; kc++) {
                        const float* gp = g_gp1 + (kc*4+b)*2048;
                        qv += gp[col]; kn += gp[512+col]; vn += gp[1024+col];
                    }
                    s_q[tid] = qv;
                    g_sK[((l*4 + b)*Tc + p)*512 + col] = kn;
                    g_sV[((l*4 + b)*Tc + p)*512 + col] = vn;
                }
                __syncthreads();
                if (tid < nk) {
                    const float4* kr4 = (const float4*)&g_sK[((l*4 + b)*Tc + tid)*512 + h*64];
                    float s = 0.f;
                    #pragma unroll
                    for (int d4 = 0; d4 < 16; d4++) {
                        float4 k4 = kr4[d4];
                        s += s_q[d4*4]*k4.x + s_q[d4*4+1]*k4.y + s_q[d4*4+2]*k4.z + s_q[d4*4+3]*k4.w;
                    }
                    s_sc[tid] = s*0.125f;
                }
                __syncthreads();
                if (tid < 64) {
                    float m = -1e30f;
                    for (int j = 0; j < nk; j++) m = fmaxf(m, s_sc[j]);
                    float ssum = 0.f, o = 0.f;
                    for (int j = 0; j < nk; j++) {
                        float e = expf(s_sc[j] - m);
                        ssum += e;
                        o += e*g_sV[((l*4 + b)*Tc + j)*512 + h*64 + tid];
                    }
                    s_ao[tid] = o/ssum;
                }
                __syncthreads();
                // o-proj: (dg, n4) split, 16 float4 loads per thread
                {
                    int dg = tid >> 7, n4 = tid & 127;
                    const float4* Wb4 = (const float4*)(sow + l*262144 + h*64*512);
                    float4 acc = {0,0,0,0};
                    #pragma unroll
                    for (int d = dg*16; d < dg*16 + 16; d++) {
                        float a = s_ao[d];
                        float4 w4 = Wb4[d*128 + n4];
                        acc.x += a*w4.x; acc.y += a*w4.y; acc.z += a*w4.z; acc.w += a*w4.w;
                    }
                    s_ws4[dg*128 + n4] = acc;
                }
                __syncthreads();
                if (tid < 128) {
                    float4 t4 = s_ws4[tid], u;
                    u = s_ws4[128 + tid]; t4.x += u.x; t4.y += u.y; t4.z += u.z; t4.w += u.w;
                    u = s_ws4[256 + tid]; t4.x += u.x; t4.y += u.y; t4.z += u.z; t4.w += u.w;
                    u = s_ws4[384 + tid]; t4.x += u.x; t4.y += u.y; t4.z += u.z; t4.w += u.w;
                    g_gp24[(h*4 + b)*128 + tid] = t4;
                }
            }
            gridbar(bar);

            // --- S3: fold heads; rms(ln2); cq partials (32 tasks)
            fold_gp2(8);
            s_xn4[tid] = s_xd4[tid]; __syncthreads();
            rms512(ln2 + l*512);
            {
                int tt = bid + warp*NB;
                if (tt < 32) {
                    int tile = tt & 3, kc = tt >> 2;
                    const float* W = cqw + l*262144;
                    int nloc = tile*128 + lane*4;
                    int k0 = kc*64;
                    float4 a0 = {0,0,0,0}, a1 = {0,0,0,0}, a2 = {0,0,0,0}, a3 = {0,0,0,0};
                    #pragma unroll 16
                    for (int k = k0; k < k0 + 64; k++) {
                        float4 w4 = *(const float4*)&W[k*512 + nloc];
                        float x0 = s_xn[k], x1 = s_xn[512+k], x2 = s_xn[1024+k], x3 = s_xn[1536+k];
                        a0.x += x0*w4.x; a0.y += x0*w4.y; a0.z += x0*w4.z; a0.w += x0*w4.w;
                        a1.x += x1*w4.x; a1.y += x1*w4.y; a1.z += x1*w4.z; a1.w += x1*w4.w;
                        a2.x += x2*w4.x; a2.y += x2*w4.y; a2.z += x2*w4.z; a2.w += x2*w4.w;
                        a3.x += x3*w4.x; a3.y += x3*w4.y; a3.z += x3*w4.z; a3.w += x3*w4.w;
                    }
                    int n4 = nloc >> 2;
                    g_gp14[(kc*4+0)*512 + n4] = a0;
                    g_gp14[(kc*4+1)*512 + n4] = a1;
                    g_gp14[(kc*4+2)*512 + n4] = a2;
                    g_gp14[(kc*4+3)*512 + n4] = a3;
                }
            }
            gridbar(bar);

            // --- S4: cross attention + co-proj (32 blocks)
            if (bid < 32) {
                int b = bid >> 3, h = bid & 7;
                if (tid < 64) {
                    float qv = 0.f;
                    #pragma unroll
                    for (int kc = 0; kc < 8; kc++) qv += g_gp1[(kc*4+b)*2048 + h*64 + tid];
                    s_q[tid] = qv;
                }
                __syncthreads();
                if (tid < 64) {
                    const float4* kr4 = (const float4*)&g_cK[((l*4 + b)*64 + tid)*512 + h*64];
                    float s = 0.f;
                    #pragma unroll
                    for (int d4 = 0; d4 < 16; d4++) {
                        float4 k4 = kr4[d4];
                        s += s_q[d4*4]*k4.x + s_q[d4*4+1]*k4.y + s_q[d4*4+2]*k4.z + s_q[d4*4+3]*k4.w;
                    }
                    s_sc[tid] = s*0.125f + (1.0f - mask[b*64 + tid])*NEGBIG;
                }
                __syncthreads();
                if (tid < 64) {
                    float m = -1e30f;
                    for (int j = 0; j < 64; j++) m = fmaxf(m, s_sc[j]);
                    s_ps[tid] = expf(s_sc[tid] - m);
                }
                __syncthreads();
                if (tid < 64) {
                    float ssum = 0.f, o = 0.f;
                    #pragma unroll 8
                    for (int j = 0; j < 64; j++) {
                        ssum += s_ps[j];
                        o += s_ps[j]*g_cV[((l*4 + b)*64 + j)*512 + h*64 + tid];
                    }
                    s_ao[tid] = o/ssum;
                }
                __syncthreads();
                {
                    int dg = tid >> 7, n4 = tid & 127;
                    const float4* Wb4 = (const float4*)(cow + l*262144 + h*64*512);
                    float4 acc = {0,0,0,0};
                    #pragma unroll
                    for (int d = dg*16; d < dg*16 + 16; d++) {
                        float a = s_ao[d];
                        float4 w4 = Wb4[d*128 + n4];
                        acc.x += a*w4.x; acc.y += a*w4.y; acc.z += a*w4.z; acc.w += a*w4.w;
                    }
                    s_ws4[dg*128 + n4] = acc;
                }
                __syncthreads();
                if (tid < 128) {
                    float4 t4 = s_ws4[tid], u;
                    u = s_ws4[128 + tid]; t4.x += u.x; t4.y += u.y; t4.z += u.z; t4.w += u.w;
                    u = s_ws4[256 + tid]; t4.x += u.x; t4.y += u.y; t4.z += u.z; t4.w += u.w;
                    u = s_ws4[384 + tid]; t4.x += u.x; t4.y += u.y; t4.z += u.z; t4.w += u.w;
                    g_gp24[(h*4 + b)*128 + tid] = t4;
                }
            }
            gridbar(bar);

            // --- S5: fold heads; rms(ln3); w1 partials (C=2048, 128 tasks)
            fold_gp2(8);
            s_xn4[tid] = s_xd4[tid]; __syncthreads();
            rms512(ln3 + l*512);
            {
                int tt = bid + warp*NB;
                if (tt < 128) {
                    int tile = tt & 15, kc = tt >> 4;
                    const float* W = w1w + l*512*2048;
                    int nloc = tile*128 + lane*4;
                    int k0 = kc*64;
                    float4 a0 = {0,0,0,0}, a1 = {0,0,0,0}, a2 = {0,0,0,0}, a3 = {0,0,0,0};
                    #pragma unroll 16
                    for (int k = k0; k < k0 + 64; k++) {
                        float4 w4 = *(const float4*)&W[k*2048 + nloc];
                        float x0 = s_xn[k], x1 = s_xn[512+k], x2 = s_xn[1024+k], x3 = s_xn[1536+k];
                        a0.x += x0*w4.x; a0.y += x0*w4.y; a0.z += x0*w4.z; a0.w += x0*w4.w;
                        a1.x += x1*w4.x; a1.y += x1*w4.y; a1.z += x1*w4.z; a1.w += x1*w4.w;
                        a2.x += x2*w4.x; a2.y += x2*w4.y; a2.z += x2*w4.z; a2.w += x2*w4.w;
                        a3.x += x3*w4.x; a3.y += x3*w4.y; a3.z += x3*w4.z; a3.w += x3*w4.w;
                    }
                    int n4 = nloc >> 2;
                    g_gp14[(kc*4+0)*2048/4 + n4] = a0;  // stride 2048 floats = 512 f4
                    g_gp14[(kc*4+1)*512 + n4] = a1;
                    g_gp14[(kc*4+2)*512 + n4] = a2;
                    g_gp14[(kc*4+3)*512 + n4] = a3;
                }
            }
            gridbar(bar);

            // --- S6: w2 (64 tasks; per-warp f combine+relu in smem, then GEMV)
            {
                int tt = bid + warp*NB;
                if (tt < 64) {
                    int tile = tt & 3, kc = tt >> 2;
                    int k0 = kc*128;
                    float* fs = s_ws + warp*512;       // f[4][128] for this k-slice
                    float4* fs4 = (float4*)fs;
                    #pragma unroll
                    for (int b = 0; b < 4; b++) {
                        float4 s = {0,0,0,0};
                        #pragma unroll
                        for (int j = 0; j < 8; j++) {
                            float4 t4 = g_gp14[(j*4+b)*512 + ((k0 + lane*4) >> 2)];
                            s.x += t4.x; s.y += t4.y; s.z += t4.z; s.w += t4.w;
                        }
                        s.x = fmaxf(s.x, 0.f); s.y = fmaxf(s.y, 0.f);
                        s.z = fmaxf(s.z, 0.f); s.w = fmaxf(s.w, 0.f);
                        fs4[b*32 + lane] = s;
                    }
                    __syncwarp();
                    const float* Wb = w2w + l*2048*512;
                    int nloc = tile*128 + lane*4;
                    float4 a0 = {0,0,0,0}, a1 = {0,0,0,0}, a2 = {0,0,0,0}, a3 = {0,0,0,0};
                    #pragma unroll 16
                    for (int kk = 0; kk < 128; kk++) {
                        float4 w4 = *(const float4*)&Wb[(k0 + kk)*512 + nloc];
                        float x0 = fs[kk], x1 = fs[128+kk], x2 = fs[256+kk], x3 = fs[384+kk];
                        a0.x += x0*w4.x; a0.y += x0*w4.y; a0.z += x0*w4.z; a0.w += x0*w4.w;
                        a1.x += x1*w4.x; a1.y += x1*w4.y; a1.z += x1*w4.z; a1.w += x1*w4.w;
                        a2.x += x2*w4.x; a2.y += x2*w4.y; a2.z += x2*w4.z; a2.w += x2*w4.w;
                        a3.x += x3*w4.x; a3.y += x3*w4.y; a3.z += x3*w4.z; a3.w += x3*w4.w;
                    }
                    int n4 = nloc >> 2;
                    g_gp24[(kc*4+0)*128 + n4] = a0;
                    g_gp24[(kc*4+1)*128 + n4] = a1;
                    g_gp24[(kc*4+2)*128 + n4] = a2;
                    g_gp24[(kc*4+3)*128 + n4] = a3;
                }
            }
            gridbar(bar);
        }

        // --- LM: fold w2(16); rms(lnf); lm partials (2008 tasks)
        fold_gp2(16);
        s_xn4[tid] = s_xd4[tid]; __syncthreads();
        rms512(lnf);
        {
            int tt = bid + warp*NB;
            if (tt < 2008) {
                int tile = tt % 251, kc = tt / 251;
                int n4 = (tile*128 + lane*4) >> 2;
                int k0 = kc*64;
                float4 a0 = {0,0,0,0}, a1 = {0,0,0,0}, a2 = {0,0,0,0}, a3 = {0,0,0,0};
                #pragma unroll 16
                for (int k = k0; k < k0 + 64; k++) {
                    float4 w4 = lm4[k*V4 + n4];
                    float x0 = s_xn[k], x1 = s_xn[512+k], x2 = s_xn[1024+k], x3 = s_xn[1536+k];
                    a0.x += x0*w4.x; a0.y += x0*w4.y; a0.z += x0*w4.z; a0.w += x0*w4.w;
                    a1.x += x1*w4.x; a1.y += x1*w4.y; a1.z += x1*w4.z; a1.w += x1*w4.w;
                    a2.x += x2*w4.x; a2.y += x2*w4.y; a2.z += x2*w4.z; a2.w += x2*w4.w;
                    a3.x += x3*w4.x; a3.y += x3*w4.y; a3.z += x3*w4.z; a3.w += x3*w4.w;
                }
                g_lmp4[(kc*4+0)*V4 + n4] = a0;
                g_lmp4[(kc*4+1)*V4 + n4] = a1;
                g_lmp4[(kc*4+2)*V4 + n4] = a2;
                g_lmp4[(kc*4+3)*V4 + n4] = a3;
            }
        }
        gridbar(bar);

        // --- LMC: combine logits + per-block max/argmax
        {
            float mv = -1e30f; int mi = 0x7fffffff; int myb = -1;
            int i4 = bid*512 + tid;
            if (i4 < 4*V4) {
                int b = i4 / V4, v4 = i4 - b*V4;
                myb = b;
                float4 s = {0,0,0,0};
                #pragma unroll
                for (int j = 0; j < 8; j++) {
                    float4 t4 = g_lmp4[(j*4+b)*V4 + v4];
                    s.x += t4.x; s.y += t4.y; s.z += t4.z; s.w += t4.w;
                }
                g_log4[b*V4 + v4] = s;
                int v0 = v4*4;
                mv = s.x; mi = v0;
                if (s.y > mv) { mv = s.y; mi = v0+1; }
                if (s.z > mv) { mv = s.z; mi = v0+2; }
                if (s.w > mv) { mv = s.w; mi = v0+3; }
            }
            #pragma unroll
            for (int b = 0; b < 4; b++) {
                s_red[tid] = (myb == b) ? mv : -1e30f;
                s_idx[tid] = (myb == b) ? mi : 0x7fffffff;
                __syncthreads();
                #pragma unroll
                for (int off = 256; off > 0; off >>= 1) {
                    if (tid < off) {
                        float v2 = s_red[tid+off]; int i2 = s_idx[tid+off];
                        if (v2 > s_red[tid] || (v2 == s_red[tid] && i2 < s_idx[tid])) {
                            s_red[tid] = v2; s_idx[tid] = i2;
                        }
                    }
                    __syncthreads();
                }
                if (tid == 0) { g_bmax[b*NB + bid] = s_red[0]; g_bmaxi[b*NB + bid] = s_idx[0]; }
                __syncthreads();
            }
        }
        gridbar(bar);

        // --- SE: global max, exp+out, emb partials (register accum)
        {
            #pragma unroll
            for (int b = 0; b < 4; b++) {
                s_red[tid] = (tid < NB) ? g_bmax[b*NB + tid] : -1e30f;
                __syncthreads();
                #pragma unroll
                for (int off = 256; off > 0; off >>= 1) {
                    if (tid < off) s_red[tid] = fmaxf(s_red[tid], s_red[tid+off]);
                    __syncthreads();
                }
                if (tid == 0) s_gmax[b] = s_red[0];
                __syncthreads();
            }
            float4 a0 = {0,0,0,0}, a1 = {0,0,0,0}, a2 = {0,0,0,0}, a3 = {0,0,0,0};
            float p_acc = 0.f;
            int eb = tid >> 7, evv = tid & 127;
            int vg = tid >> 7, d4 = tid & 127;
            for (int ch = bid; ch < 251; ch += NB) {
                int v0 = ch*128;
                {
                    float e = expf(g_logits[eb*Vc + v0 + evv] - s_gmax[eb]);
                    s_ev[eb*128 + evv] = e;
                    out[((size_t)eb*Tc + p)*Vc + v0 + evv] = e;
                    p_acc += e;
                }
                __syncthreads();
                #pragma unroll 8
                for (int v = vg*32; v < vg*32 + 32; v++) {
                    float4 w4 = emb4[(size_t)(v0 + v)*128 + d4];
                    float e0 = s_ev[v], e1 = s_ev[128+v], e2 = s_ev[256+v], e3 = s_ev[384+v];
                    a0.x += e0*w4.x; a0.y += e0*w4.y; a0.z += e0*w4.z; a0.w += e0*w4.w;
                    a1.x += e1*w4.x; a1.y += e1*w4.y; a1.z += e1*w4.z; a1.w += e1*w4.w;
                    a2.x += e2*w4.x; a2.y += e2*w4.y; a2.z += e2*w4.z; a2.w += e2*w4.w;
                    a3.x += e3*w4.x; a3.y += e3*w4.y; a3.z += e3*w4.z; a3.w += e3*w4.w;
                }
                __syncthreads();
            }
            // vg-partials -> smem -> per-block sums
            s_ws4[vg*512 + 0*128 + d4] = a0;
            s_ws4[vg*512 + 1*128 + d4] = a1;
            s_ws4[vg*512 + 2*128 + d4] = a2;
            s_ws4[vg*512 + 3*128 + d4] = a3;
            __syncthreads();
            {
                float4 t4 = s_ws4[tid], u;
                u = s_ws4[512 + tid];  t4.x += u.x; t4.y += u.y; t4.z += u.z; t4.w += u.w;
                u = s_ws4[1024 + tid]; t4.x += u.x; t4.y += u.y; t4.z += u.z; t4.w += u.w;
                u = s_ws4[1536 + tid]; t4.x += u.x; t4.y += u.y; t4.z += u.z; t4.w += u.w;
                g_sepB4[bid*512 + tid] = t4;
            }
            // psum per b
            s_red[tid] = p_acc; __syncthreads();
            #pragma unroll
            for (int off = 64; off > 0; off >>= 1) {
                if ((tid & 127) < off) s_red[tid] += s_red[tid + off];
                __syncthreads();
            }
            if ((tid & 127) == 0) g_psumB[bid*4 + (tid >> 7)] = s_red[tid];
        }
        gridbar(bar);

        // --- FIN: inv, normalize out, xd, flags
        {
            #pragma unroll
            for (int b = 0; b < 4; b++) {
                s_red[tid] = (tid < NB) ? g_psumB[tid*4 + b] : 0.f;
                __syncthreads();
                #pragma unroll
                for (int off = 256; off > 0; off >>= 1) {
                    if (tid < off) s_red[tid] += s_red[tid + off];
                    __syncthreads();
                }
                if (tid == 0) s_rsc[b] = 1.0f / s_red[0];
                __syncthreads();
            }
            int i4 = bid*512 + tid;
            if (i4 < 4*V4) {
                int b = i4 / V4, v4 = i4 - b*V4;
                float4 t4 = out4[((size_t)b*Tc + p)*V4 + v4];
                float inv = s_rsc[b];
                t4.x *= inv; t4.y *= inv; t4.z *= inv; t4.w *= inv;
                out4[((size_t)b*Tc + p)*V4 + v4] = t4;
            }
            if (bid == 0) {
                int b = tid >> 7;
                float4 s = {0,0,0,0};
                #pragma unroll 8
                for (int blk = 0; blk < NB; blk++) {
                    float4 t4 = g_sepB4[blk*512 + tid];
                    s.x += t4.x; s.y += t4.y; s.z += t4.z; s.w += t4.w;
                }
                float inv = s_rsc[b];
                s.x *= inv; s.y *= inv; s.z *= inv; s.w *= inv;
                g_xd4[tid] = s;
            }
            if (bid == 1 && flagOK) {
                #pragma unroll
                for (int b = 0; b < 4; b++) {
                    s_red[tid] = (tid < NB) ? g_bmax[b*NB + tid] : -1e30f;
                    s_idx[tid] = (tid < NB) ? g_bmaxi[b*NB + tid] : 0x7fffffff;
                    __syncthreads();
                    #pragma unroll
                    for (int off = 256; off > 0; off >>= 1) {
                        if (tid < off) {
                            float v2 = s_red[tid+off]; int i2 = s_idx[tid+off];
                            if (v2 > s_red[tid] || (v2 == s_red[tid] && i2 < s_idx[tid])) {
                                s_red[tid] = v2; s_idx[tid] = i2;
                            }
                        }
                        __syncthreads();
                    }
                    if (tid == 0)
                        out[(size_t)Bc*Tc*Vc + b*Tc + p] = (s_idx[0] == 0) ? 1.0f : 0.0f;
                    __syncthreads();
                }
            }
        }
        gridbar(bar);
    }

    // end-of-kernel counter reset handshake
    __syncthreads();
    if (tid == 0)
        asm volatile("red.release.gpu.global.add.u32 [%0], 1;" :: "l"(&g_done) : "memory");
    if (bid == 0 && tid == 0) {
        unsigned int v;
        do {
            asm volatile("ld.acquire.gpu.global.u32 %0, [%1];" : "=r"(v) : "l"(&g_done) : "memory");
        } while (v < NB);
        g_ctr = 0;
        g_done = 0;
    }
}

// ======================= host =======================
extern "C" void kernel_launch(void* const* d_in, const int* in_sizes, int n_in,
                              void* d_out, int out_size) {
    const int*   ids     = (const int*)d_in[0];
    const float* mask    = (const float*)d_in[1];
    const float* emb     = (const float*)d_in[2];
    const float* enc_wq  = (const float*)d_in[3];
    const float* enc_wk  = (const float*)d_in[4];
    const float* enc_wv  = (const float*)d_in[5];
    const float* enc_wo  = (const float*)d_in[6];
    const float* enc_ln1 = (const float*)d_in[7];
    const float* enc_w1  = (const float*)d_in[8];
    const float* enc_w2  = (const float*)d_in[9];
    const float* enc_ln2 = (const float*)d_in[10];
    const float* enc_lnf = (const float*)d_in[11];
    const float* dec_sq  = (const float*)d_in[12];
    const float* dec_sk  = (const float*)d_in[13];
    const float* dec_sv  = (const float*)d_in[14];
    const float* dec_so  = (const float*)d_in[15];
    const float* dec_ln1 = (const float*)d_in[16];
    const float* dec_cq  = (const float*)d_in[17];
    const float* dec_ck  = (const float*)d_in[18];
    const float* dec_cv  = (const float*)d_in[19];
    const float* dec_co  = (const float*)d_in[20];
    const float* dec_ln2 = (const float*)d_in[21];
    const float* dec_w1  = (const float*)d_in[22];
    const float* dec_w2  = (const float*)d_in[23];
    const float* dec_ln3 = (const float*)d_in[24];
    const float* dec_lnf = (const float*)d_in[25];
    const float* lm      = (const float*)d_in[26];
    float* out = (float*)d_out;

    void* vp;
    cudaGetSymbolAddress(&vp, g_x);   float* px   = (float*)vp;
    cudaGetSymbolAddress(&vp, g_h);   float* ph   = (float*)vp;
    cudaGetSymbolAddress(&vp, g_q);   float* pq   = (float*)vp;
    cudaGetSymbolAddress(&vp, g_k);   float* pk   = (float*)vp;
    cudaGetSymbolAddress(&vp, g_v);   float* pv   = (float*)vp;
    cudaGetSymbolAddress(&vp, g_att); float* patt = (float*)vp;
    cudaGetSymbolAddress(&vp, g_ff);  float* pff  = (float*)vp;
    cudaGetSymbolAddress(&vp, g_hs);  float* phs  = (float*)vp;
    cudaGetSymbolAddress(&vp, g_cK);  float* pcK  = (float*)vp;
    cudaGetSymbolAddress(&vp, g_cV);  float* pcV  = (float*)vp;

    static bool attrSet = false;
    if (!attrSet) {
        cudaFuncSetAttribute(decode_k, cudaFuncAttributeMaxDynamicSharedMemorySize, 49152);
        attrSet = true;
    }

    const int M = Bc*Sc;  // 256

    // ---------- encoder ----------
    embed_k<<<M, 256>>>(ids, emb);
    for (int l = 0; l < Lc; l++) {
        rmsnorm_k<<<M, 256>>>(px, ph, enc_ln1 + l*Dc);
        gemm_k<<<dim3(8, 4, 3), 256>>>(ph,
            enc_wq + l*Dc*Dc, pq, enc_wk + l*Dc*Dc, pk, enc_wv + l*Dc*Dc, pv,
            nullptr, nullptr, M, Dc, Dc, nullptr, 0);
        encattn_k<<<Bc*Hc*Sc, 64>>>(mask);
        gemm_k<<<dim3(8, 4, 1), 256>>>(patt,
            enc_wo + l*Dc*Dc, px, nullptr, nullptr, nullptr, nullptr, nullptr, nullptr,
            M, Dc, Dc, px, 0);
        rmsnorm_k<<<M, 256>>>(px, ph, enc_ln2 + l*Dc);
        gemm_k<<<dim3(32, 4, 1), 256>>>(ph,
            enc_w1 + l*Dc*Fc, pff, nullptr, nullptr, nullptr, nullptr, nullptr, nullptr,
            M, Fc, Dc, nullptr, 1);
        gemm_k<<<dim3(8, 4, 1), 256>>>(pff,
            enc_w2 + l*Fc*Dc, px, nullptr, nullptr, nullptr, nullptr, nullptr, nullptr,
            M, Dc, Fc, px, 0);
    }
    rmsnorm_k<<<M, 256>>>(px, phs, enc_lnf);

    gemm_k<<<dim3(8, 4, 4), 256>>>(phs,
        dec_ck,           pcK,
        dec_cv,           pcV,
        dec_ck + Dc*Dc,   pcK + Bc*Sc*Dc,
        dec_cv + Dc*Dc,   pcV + Bc*Sc*Dc,
        M, Dc, Dc, nullptr, 0);

    // ---------- decoder megakernel ----------
    int flagOK = (out_size >= Bc*Tc*Vc + Bc*Tc) ? 1 : 0;
    decode_k<<<NB, 512, 49152>>>(mask, emb,
        dec_sq, dec_sk, dec_sv, dec_so, dec_ln1,
        dec_cq, dec_co, dec_ln2,
        dec_w1, dec_w2, dec_ln3,
        dec_lnf, lm, out, flagOK);
}